// round 4
// baseline (speedup 1.0000x reference)
#include <cuda_runtime.h>

#define BB 32768
#define TT 78
#define HH 27
#define GG 108   // 4*H

// Scratch (device globals; accessed ONLY from device code)
static __device__ float4 g_xg[(size_t)BB * TT * HH];   // gate preactivations, gate-packed
static __device__ float  g_hbuf[(size_t)BB * TT * HH]; // inter-layer activations

__device__ __forceinline__ float sigf(float x) {
    return __fdividef(1.0f, 1.0f + __expf(-x));
}
__device__ __forceinline__ float tanhfast(float x) {
    return __fdividef(2.0f, 1.0f + __expf(-2.0f * x)) - 1.0f;
}

// ---------- packed f32x2 helpers ----------
__device__ __forceinline__ unsigned long long pack2(float lo, float hi) {
    unsigned long long r;
    asm("mov.b64 %0, {%1, %2};" : "=l"(r) : "f"(lo), "f"(hi));
    return r;
}
__device__ __forceinline__ void unpack2(unsigned long long v, float& lo, float& hi) {
    asm("mov.b64 {%0, %1}, %2;" : "=f"(lo), "=f"(hi) : "l"(v));
}
__device__ __forceinline__ unsigned long long fma2(unsigned long long a, unsigned long long b,
                                                   unsigned long long c) {
    unsigned long long d;
    asm("fma.rn.f32x2 %0, %1, %2, %3;" : "=l"(d) : "l"(a), "l"(b), "l"(c));
    return d;
}

// ================= Phase A: xg[r][j] = bias[j] + sum_k in[r][k] * Wih[:,j,k] =================
// Block handles 256 rows (thread = row pair, f32x2). All gmem I/O staged through SMEM
// so LDG/STG are coalesced; compute reads broadcast weights from SMEM.

#define WSTRIDE 28   // padded j-stride for weight table (j=27 column is zero)

__global__ void __launch_bounds__(128, 4)
phaseA_kernel(const float* __restrict__ xin,
              const float* __restrict__ Wih,
              const float* __restrict__ bih,
              const float* __restrict__ bhh,
              int src)                               // 0: xin, 1: g_hbuf (device-side select)
{
    __shared__ alignas(16) unsigned long long Ws[HH * WSTRIDE * 4];  // [k][j(pad28)][g] splats
    __shared__ unsigned long long Bs[WSTRIDE * 4];
    __shared__ alignas(16) float buf[4096];   // 16KB: input stage (3456 floats) / output stage

    const int tid = threadIdx.x;

    for (int i = tid; i < HH * WSTRIDE * 4; i += 128) {
        int g = i & 3, j = (i >> 2) % WSTRIDE, k = (i >> 2) / WSTRIDE;
        float w = (j < HH) ? Wih[(g * HH + j) * HH + k] : 0.f;
        Ws[i] = pack2(w, w);
    }
    for (int i = tid; i < WSTRIDE * 4; i += 128) {
        int g = i & 3, j = i >> 2;
        float b = (j < HH) ? (bih[g * HH + j] + bhh[g * HH + j]) : 0.f;
        Bs[i] = pack2(b, b);
    }

    const float* in = (src == 0) ? xin : (const float*)g_hbuf;
    const size_t rowBase = (size_t)blockIdx.x * 256;

    // Stage input rows through SMEM in two 128-row halves; build packed px in regs.
    unsigned long long px[HH];
    const int myhalf = tid >> 6;
    const int pl = tid & 63;
#pragma unroll
    for (int half = 0; half < 2; ++half) {
        __syncthreads();
        const float* gsrc = in + (rowBase + (size_t)half * 128) * HH;
        for (int i = tid; i < 128 * HH; i += 128) buf[i] = gsrc[i];   // coalesced
        __syncthreads();
        if (myhalf == half) {
#pragma unroll
            for (int k = 0; k < HH; ++k)
                px[k] = pack2(buf[pl * 54 + k], buf[pl * 54 + HH + k]);
        }
    }
    __syncthreads();

    float4* os = reinterpret_cast<float4*>(buf);

    // 7 chunks of 4 gate-columns (last chunk: only 3 flushed; j=27 is zero-padded)
    for (int cb = 0; cb < 7; ++cb) {
        const int jbase = cb * 4;

        unsigned long long acc[4][4];
#pragma unroll
        for (int jj = 0; jj < 4; ++jj)
#pragma unroll
            for (int g = 0; g < 4; ++g) acc[jj][g] = Bs[(jbase + jj) * 4 + g];

#pragma unroll
        for (int k = 0; k < HH; ++k) {
            unsigned long long xk = px[k];
#pragma unroll
            for (int jj = 0; jj < 4; ++jj) {
                const ulonglong2* wp =
                    reinterpret_cast<const ulonglong2*>(Ws + (size_t)(k * WSTRIDE + jbase + jj) * 4);
                ulonglong2 w01 = wp[0];
                ulonglong2 w23 = wp[1];
                acc[jj][0] = fma2(xk, w01.x, acc[jj][0]);
                acc[jj][1] = fma2(xk, w01.y, acc[jj][1]);
                acc[jj][2] = fma2(xk, w23.x, acc[jj][2]);
                acc[jj][3] = fma2(xk, w23.y, acc[jj][3]);
            }
        }

        // stage to SMEM (rows 2*tid, 2*tid+1)
#pragma unroll
        for (int jj = 0; jj < 4; ++jj) {
            float4 lo4, hi4;
            unpack2(acc[jj][0], lo4.x, hi4.x);
            unpack2(acc[jj][1], lo4.y, hi4.y);
            unpack2(acc[jj][2], lo4.z, hi4.z);
            unpack2(acc[jj][3], lo4.w, hi4.w);
            os[(2 * tid)     * 4 + jj] = lo4;
            os[(2 * tid + 1) * 4 + jj] = hi4;
        }
        __syncthreads();

        // cooperative coalesced flush
        const int JN = (cb == 6) ? 3 : 4;
        const int total = 256 * JN;
        for (int idx = tid; idx < total; idx += 128) {
            int r, jj;
            if (JN == 4) { r = idx >> 2; jj = idx & 3; }
            else         { r = idx / 3;  jj = idx % 3; }
            g_xg[(rowBase + r) * HH + jbase + jj] = os[r * 4 + jj];
        }
        __syncthreads();
    }
}

// ================= Phase B: recurrence. One warp per batch element; lane j owns gate column j.
// i/g/o gate weights in registers; f gate weights in SMEM (lane-indexed, conflict-free).
// h exchanged via float4-readable per-warp SMEM row; c in a register.

template<bool DOLIN>
__global__ void __launch_bounds__(128, 4)
phaseB_kernel(const float* __restrict__ h0,
              const float* __restrict__ c0,
              const float* __restrict__ Whh,
              const float* __restrict__ Wl,
              const float* __restrict__ bl,
              float* __restrict__ dout)
{
    __shared__ alignas(16) float hs[2][4][32];   // ping-pong h per warp, zero-padded 27..31
    __shared__ alignas(16) float4 Wf4[7][32];    // f-gate weights: [k/4][lane j]
    __shared__ alignas(16) float4 Wl4[32][8];    // linear weights row-major padded
    __shared__ float bls[32];

    const int tid = threadIdx.x;
    const int w   = tid >> 5;
    const int j   = tid & 31;
    const bool act = (j < HH);
    const int jj = act ? j : 0;

    // f-gate weight table: Wf4[q][lane].c = Whh[(HH + lane)*HH + 4q+c], zero-padded
    for (int i = tid; i < 7 * 32; i += 128) {
        int q = i >> 5, lj = i & 31;
        float4 v;
        v.x = (lj < HH && 4 * q + 0 < HH) ? Whh[(HH + lj) * HH + 4 * q + 0] : 0.f;
        v.y = (lj < HH && 4 * q + 1 < HH) ? Whh[(HH + lj) * HH + 4 * q + 1] : 0.f;
        v.z = (lj < HH && 4 * q + 2 < HH) ? Whh[(HH + lj) * HH + 4 * q + 2] : 0.f;
        v.w = (lj < HH && 4 * q + 3 < HH) ? Whh[(HH + lj) * HH + 4 * q + 3] : 0.f;
        Wf4[q][lj] = v;
    }
    if (DOLIN) {
        for (int i = tid; i < 32 * 7; i += 128) {
            int r = i / 7, q = i % 7;
            float4 v;
            v.x = (r < HH && 4 * q + 0 < HH) ? Wl[r * HH + 4 * q + 0] : 0.f;
            v.y = (r < HH && 4 * q + 1 < HH) ? Wl[r * HH + 4 * q + 1] : 0.f;
            v.z = (r < HH && 4 * q + 2 < HH) ? Wl[r * HH + 4 * q + 2] : 0.f;
            v.w = (r < HH && 4 * q + 3 < HH) ? Wl[r * HH + 4 * q + 3] : 0.f;
            Wl4[r][q] = v;
        }
        if (tid < 32) bls[tid] = (tid < HH) ? bl[tid] : 0.f;
    }

    const size_t b = (size_t)blockIdx.x * 4 + w;

    // i, g, o gate columns in registers (zero-padded to 28)
    float wi[28], wg[28], wo[28];
#pragma unroll
    for (int k = 0; k < HH; ++k) {
        wi[k] = Whh[(0 * HH + jj) * HH + k];
        wg[k] = Whh[(2 * HH + jj) * HH + k];
        wo[k] = Whh[(3 * HH + jj) * HH + k];
    }
    wi[27] = wg[27] = wo[27] = 0.f;

    float c = act ? c0[b * HH + j] : 0.f;
    hs[0][w][j] = act ? h0[b * HH + j] : 0.f;
    hs[1][w][j] = 0.f;
    __syncthreads();

    const float4* xp = g_xg + b * (size_t)(TT * HH);
    float* op = (DOLIN ? dout : g_hbuf) + b * (size_t)(TT * HH);

    float4 xv = act ? xp[j] : make_float4(0.f, 0.f, 0.f, 0.f);
    int p = 0;

    for (int t = 0; t < TT; ++t) {
        float4 xn = make_float4(0.f, 0.f, 0.f, 0.f);
        if (t + 1 < TT && act) xn = xp[(t + 1) * HH + j];

        const float4* hp = reinterpret_cast<const float4*>(&hs[p][w][0]);

        float ai0 = xv.x, ai1 = 0.f;
        float af0 = xv.y, af1 = 0.f;
        float ag0 = xv.z, ag1 = 0.f;
        float ao0 = xv.w, ao1 = 0.f;
#pragma unroll
        for (int q = 0; q < 7; ++q) {
            float4 h4 = hp[q];
            float4 wf = Wf4[q][j];
            int k = 4 * q;
            ai0 = fmaf(wi[k + 0], h4.x, ai0);
            ai1 = fmaf(wi[k + 1], h4.y, ai1);
            ai0 = fmaf(wi[k + 2], h4.z, ai0);
            ai1 = fmaf(wi[k + 3], h4.w, ai1);
            af0 = fmaf(wf.x, h4.x, af0);
            af1 = fmaf(wf.y, h4.y, af1);
            af0 = fmaf(wf.z, h4.z, af0);
            af1 = fmaf(wf.w, h4.w, af1);
            ag0 = fmaf(wg[k + 0], h4.x, ag0);
            ag1 = fmaf(wg[k + 1], h4.y, ag1);
            ag0 = fmaf(wg[k + 2], h4.z, ag0);
            ag1 = fmaf(wg[k + 3], h4.w, ag1);
            ao0 = fmaf(wo[k + 0], h4.x, ao0);
            ao1 = fmaf(wo[k + 1], h4.y, ao1);
            ao0 = fmaf(wo[k + 2], h4.z, ao0);
            ao1 = fmaf(wo[k + 3], h4.w, ao1);
        }

        float gi = sigf(ai0 + ai1);
        float gf = sigf(af0 + af1);
        float gg = tanhfast(ag0 + ag1);
        float go = sigf(ao0 + ao1);
        c = fmaf(gf, c, gi * gg);
        float hn = go * tanhfast(c);

        if (act) hs[p ^ 1][w][j] = hn;
        __syncwarp();

        if (DOLIN) {
            const float4* hq = reinterpret_cast<const float4*>(&hs[p ^ 1][w][0]);
            float l0 = bls[jj], l1 = 0.f;
#pragma unroll
            for (int q = 0; q < 7; ++q) {
                float4 h4 = hq[q];
                float4 wl = Wl4[jj][q];
                l0 = fmaf(wl.x, h4.x, l0);
                l1 = fmaf(wl.y, h4.y, l1);
                l0 = fmaf(wl.z, h4.z, l0);
                l1 = fmaf(wl.w, h4.w, l1);
            }
            if (act) op[t * HH + j] = l0 + l1;
        } else {
            if (act) op[t * HH + j] = hn;
        }

        p ^= 1;
        xv = xn;
    }
}

// ================= host =================
extern "C" void kernel_launch(void* const* d_in, const int* in_sizes, int n_in,
                              void* d_out, int out_size)
{
    const float* x   = (const float*)d_in[0];
    const float* h0  = (const float*)d_in[1];
    const float* c0  = (const float*)d_in[2];
    const float* Wih = (const float*)d_in[3];
    const float* Whh = (const float*)d_in[4];
    const float* bih = (const float*)d_in[5];
    const float* bhh = (const float*)d_in[6];
    const float* Wl  = (const float*)d_in[7];
    const float* bl  = (const float*)d_in[8];
    float* out = (float*)d_out;

    const size_t st = (size_t)BB * HH;
    const size_t wS = (size_t)GG * HH;
    const size_t bS = (size_t)GG;

    const int gridA = (BB * TT) / 256;   // 9984, exact
    const int gridB = BB / 4;            // 8192, exact

    // Layer 0
    phaseA_kernel<<<gridA, 128>>>(x, Wih, bih, bhh, 0);
    phaseB_kernel<false><<<gridB, 128>>>(h0, c0, Whh, Wl, bl, out);
    // Layer 1
    phaseA_kernel<<<gridA, 128>>>(x, Wih + wS, bih + bS, bhh + bS, 1);
    phaseB_kernel<false><<<gridB, 128>>>(h0 + st, c0 + st, Whh + wS, Wl, bl, out);
    // Layer 2 (+ fused linear head)
    phaseA_kernel<<<gridA, 128>>>(x, Wih + 2 * wS, bih + 2 * bS, bhh + 2 * bS, 1);
    phaseB_kernel<true><<<gridB, 128>>>(h0 + 2 * st, c0 + 2 * st, Whh + 2 * wS, Wl, bl, out);
}

// round 5
// speedup vs baseline: 1.0176x; 1.0176x over previous
#include <cuda_runtime.h>

#define BB 32768
#define TT 78
#define HH 27
#define GG 108   // 4*H

// Scratch (device globals; accessed ONLY from device code)
static __device__ float4 g_xg[(size_t)BB * TT * HH];   // gate preactivations, gate-packed
static __device__ float  g_hbuf[(size_t)BB * TT * HH]; // inter-layer activations

__device__ __forceinline__ float sigf(float x) {
    return __fdividef(1.0f, 1.0f + __expf(-x));
}
__device__ __forceinline__ float tanhfast(float x) {
    return __fdividef(2.0f, 1.0f + __expf(-2.0f * x)) - 1.0f;
}

// ---------- packed f32x2 helpers ----------
__device__ __forceinline__ unsigned long long pack2(float lo, float hi) {
    unsigned long long r;
    asm("mov.b64 %0, {%1, %2};" : "=l"(r) : "f"(lo), "f"(hi));
    return r;
}
__device__ __forceinline__ void unpack2(unsigned long long v, float& lo, float& hi) {
    asm("mov.b64 {%0, %1}, %2;" : "=f"(lo), "=f"(hi) : "l"(v));
}
__device__ __forceinline__ unsigned long long fma2(unsigned long long a, unsigned long long b,
                                                   unsigned long long c) {
    unsigned long long d;
    asm("fma.rn.f32x2 %0, %1, %2, %3;" : "=l"(d) : "l"(a), "l"(b), "l"(c));
    return d;
}
__device__ __forceinline__ unsigned long long add2(unsigned long long a, unsigned long long b) {
    unsigned long long d;
    asm("add.rn.f32x2 %0, %1, %2;" : "=l"(d) : "l"(a), "l"(b));
    return d;
}

// ================= Phase A =================
// Block = 256 rows, 128 threads; thread = row pair (2*tid, 2*tid+1) packed f32x2.
// Input staged transposed in SMEM (conflict-free), output staged per j-chunk with
// padded stride then flushed with 64B-contiguous STG segments.

#define AROWS 256
#define XSTR 131   // odd stride for transposed x stage

__global__ void __launch_bounds__(128, 4)
phaseA_kernel(const float* __restrict__ xin,
              const float* __restrict__ Wih,
              const float* __restrict__ bih,
              const float* __restrict__ bhh,
              int src)                               // 0: xin, 1: g_hbuf (device-side select)
{
    __shared__ alignas(16) unsigned long long Ws2[(HH * HH + 1) * 4]; // [k][j][g] splats (+zero slot)
    __shared__ unsigned long long Bs[(HH + 1) * 4];
    __shared__ alignas(16) float pool[5120];  // union: x_s[27][131] (3537 fl) / os4 (1280 float4)

    const int tid = threadIdx.x;

    // weight splat table: Ws2[(k*27 + j)*4 + g] = (w,w); extra slot (k*27+j == 729) = 0
    for (int i = tid; i < (HH * HH + 1) * 4; i += 128) {
        int g = i & 3, kj = i >> 2;
        float w = 0.f;
        if (kj < HH * HH) {
            int k = kj / HH, j = kj - k * HH;
            w = Wih[(g * HH + j) * HH + k];
        }
        Ws2[i] = pack2(w, w);
    }
    for (int i = tid; i < (HH + 1) * 4; i += 128) {
        int g = i & 3, j = i >> 2;
        float b = (j < HH) ? (bih[g * HH + j] + bhh[g * HH + j]) : 0.f;
        Bs[i] = pack2(b, b);
    }

    const float* in = (src == 0) ? xin : (const float*)g_hbuf;
    const size_t rowBase = (size_t)blockIdx.x * AROWS;

    // Stage input transposed, two 128-row passes; build px in regs.
    unsigned long long px[HH];
    const int myhalf = tid >> 6;
    const int pl = tid & 63;
#pragma unroll 1
    for (int half = 0; half < 2; ++half) {
        __syncthreads();
        const float* gsrc = in + (rowBase + (size_t)half * 128) * HH;
        for (int i = tid; i < 128 * HH; i += 128) {      // coalesced LDG
            int r = i / HH, k = i - r * HH;
            pool[k * XSTR + r] = gsrc[i];                // conflict-free STS (131 odd)
        }
        __syncthreads();
        if (myhalf == half) {
#pragma unroll
            for (int k = 0; k < HH; ++k)
                px[k] = pack2(pool[k * XSTR + 2 * pl], pool[k * XSTR + 2 * pl + 1]); // 2-way
        }
    }
    __syncthreads();

    float4* os4 = reinterpret_cast<float4*>(pool);

#pragma unroll 1
    for (int cb = 0; cb < 7; ++cb) {
        const int jbase = cb * 4;

        unsigned long long acc[4][4];
#pragma unroll
        for (int jj = 0; jj < 4; ++jj)
#pragma unroll
            for (int g = 0; g < 4; ++g) acc[jj][g] = Bs[(jbase + jj) * 4 + g];

#pragma unroll
        for (int k = 0; k < HH; ++k) {
            unsigned long long xk = px[k];
#pragma unroll
            for (int jj = 0; jj < 4; ++jj) {
                const ulonglong2* wp =
                    reinterpret_cast<const ulonglong2*>(Ws2 + (size_t)((k * HH + jbase + jj) * 4));
                ulonglong2 w01 = wp[0];
                ulonglong2 w23 = wp[1];
                acc[jj][0] = fma2(xk, w01.x, acc[jj][0]);
                acc[jj][1] = fma2(xk, w01.y, acc[jj][1]);
                acc[jj][2] = fma2(xk, w23.x, acc[jj][2]);
                acc[jj][3] = fma2(xk, w23.y, acc[jj][3]);
            }
        }

        // stage to SMEM with stride-5 float4 rows (2-way max conflicts)
#pragma unroll
        for (int jj = 0; jj < 4; ++jj) {
            float4 lo4, hi4;
            unpack2(acc[jj][0], lo4.x, hi4.x);
            unpack2(acc[jj][1], lo4.y, hi4.y);
            unpack2(acc[jj][2], lo4.z, hi4.z);
            unpack2(acc[jj][3], lo4.w, hi4.w);
            os4[(2 * tid)     * 5 + jj] = lo4;
            os4[(2 * tid + 1) * 5 + jj] = hi4;
        }
        __syncthreads();

        // flush: warp covers 8 rows x 4 jj -> 64B-contiguous segments (8 wavefronts/STG)
        for (int it = 0; it < 8; ++it) {
            int e = it * 128 + tid;
            int r = e >> 2, jj = e & 3;
            if (jbase + jj < HH)
                g_xg[(rowBase + r) * HH + jbase + jj] = os4[r * 5 + jj];
        }
        __syncthreads();
    }
}

// ================= Phase B =================
// One warp per batch element; lane j owns gate pairs (i,f) and (g,o) as f32x2.
// Whh staged through SMEM (coalesced) then into per-lane u64 weight regs.
// h exchanged as splatted u64 pairs in SMEM; c in a register.

template<bool DOLIN>
__global__ void __launch_bounds__(128, 3)
phaseB_kernel(const float* __restrict__ h0,
              const float* __restrict__ c0,
              const float* __restrict__ Whh,
              const float* __restrict__ Wl,
              const float* __restrict__ bl,
              float* __restrict__ dout)
{
    __shared__ alignas(16) unsigned long long hs2[4][2][32]; // splatted h, ping-pong, pad 27..31
    __shared__ float whh_s[GG * HH];                          // staged Whh (11.7KB)
    __shared__ alignas(16) float hs_lin[4][2][32];            // plain h for linear head
    __shared__ alignas(16) float4 Wl4[32][8];
    __shared__ float bls[32];

    const int tid = threadIdx.x;
    const int w   = tid >> 5;
    const int j   = tid & 31;
    const bool act = (j < HH);
    const int jj = act ? j : 0;

    for (int i = tid; i < GG * HH; i += 128) whh_s[i] = Whh[i];   // coalesced
    if (DOLIN) {
        for (int i = tid; i < 32 * 7; i += 128) {
            int r = i / 7, q = i % 7;
            float4 v;
            v.x = (r < HH && 4 * q + 0 < HH) ? Wl[r * HH + 4 * q + 0] : 0.f;
            v.y = (r < HH && 4 * q + 1 < HH) ? Wl[r * HH + 4 * q + 1] : 0.f;
            v.z = (r < HH && 4 * q + 2 < HH) ? Wl[r * HH + 4 * q + 2] : 0.f;
            v.w = (r < HH && 4 * q + 3 < HH) ? Wl[r * HH + 4 * q + 3] : 0.f;
            Wl4[r][q] = v;
        }
        if (tid < 32) bls[tid] = (tid < HH) ? bl[tid] : 0.f;
    }
    __syncthreads();

    // gate-pair packed weights in regs (stride-729 LDS: 729%32=25 -> conflict-free)
    unsigned long long wif[28], wgo[28];
#pragma unroll
    for (int k = 0; k < HH; ++k) {
        wif[k] = pack2(whh_s[(0 * HH + jj) * HH + k], whh_s[(1 * HH + jj) * HH + k]);
        wgo[k] = pack2(whh_s[(2 * HH + jj) * HH + k], whh_s[(3 * HH + jj) * HH + k]);
    }
    wif[27] = 0ull;
    wgo[27] = 0ull;

    const size_t b = (size_t)blockIdx.x * 4 + w;

    float c = act ? c0[b * HH + j] : 0.f;
    float hinit = act ? h0[b * HH + j] : 0.f;
    hs2[w][0][j] = pack2(hinit, hinit);
    hs2[w][1][j] = 0ull;
    if (DOLIN) { hs_lin[w][0][j] = hinit; hs_lin[w][1][j] = 0.f; }
    __syncwarp();

    const float4* xp = g_xg + b * (size_t)(TT * HH);
    float* op = (DOLIN ? dout : g_hbuf) + b * (size_t)(TT * HH);

    float4 xv = act ? xp[j] : make_float4(0.f, 0.f, 0.f, 0.f);
    int p = 0;

    for (int t = 0; t < TT; ++t) {
        float4 xn = make_float4(0.f, 0.f, 0.f, 0.f);
        if (t + 1 < TT && act) xn = xp[(t + 1) * HH + j];

        const ulonglong2* hp = reinterpret_cast<const ulonglong2*>(&hs2[w][p][0]);

        unsigned long long aif0 = pack2(xv.x, xv.y);
        unsigned long long ago0 = pack2(xv.z, xv.w);
        unsigned long long aif1 = 0ull, ago1 = 0ull;
#pragma unroll
        for (int q = 0; q < 14; ++q) {
            ulonglong2 h2 = hp[q];                 // broadcast LDS.128: (h2k,h2k,h2k+1,h2k+1)
            aif0 = fma2(h2.x, wif[2 * q],     aif0);
            ago0 = fma2(h2.x, wgo[2 * q],     ago0);
            aif1 = fma2(h2.y, wif[2 * q + 1], aif1);
            ago1 = fma2(h2.y, wgo[2 * q + 1], ago1);
        }

        unsigned long long aif = add2(aif0, aif1);
        unsigned long long ago = add2(ago0, ago1);
        float ai, af, ag, ao;
        unpack2(aif, ai, af);
        unpack2(ago, ag, ao);

        float gi = sigf(ai);
        float gf = sigf(af);
        float gg = tanhfast(ag);
        float go = sigf(ao);
        c = fmaf(gf, c, gi * gg);
        float hn = go * tanhfast(c);

        if (act) {
            hs2[w][p ^ 1][j] = pack2(hn, hn);
            if (DOLIN) hs_lin[w][p ^ 1][j] = hn;
        }
        __syncwarp();

        if (DOLIN) {
            const float4* hq = reinterpret_cast<const float4*>(&hs_lin[w][p ^ 1][0]);
            float l0 = bls[jj], l1 = 0.f;
#pragma unroll
            for (int q = 0; q < 7; ++q) {
                float4 h4 = hq[q];
                float4 wl = Wl4[jj][q];
                l0 = fmaf(wl.x, h4.x, l0);
                l1 = fmaf(wl.y, h4.y, l1);
                l0 = fmaf(wl.z, h4.z, l0);
                l1 = fmaf(wl.w, h4.w, l1);
            }
            if (act) op[t * HH + j] = l0 + l1;
        } else {
            if (act) op[t * HH + j] = hn;
        }

        p ^= 1;
        xv = xn;
    }
}

// ================= host =================
extern "C" void kernel_launch(void* const* d_in, const int* in_sizes, int n_in,
                              void* d_out, int out_size)
{
    const float* x   = (const float*)d_in[0];
    const float* h0  = (const float*)d_in[1];
    const float* c0  = (const float*)d_in[2];
    const float* Wih = (const float*)d_in[3];
    const float* Whh = (const float*)d_in[4];
    const float* bih = (const float*)d_in[5];
    const float* bhh = (const float*)d_in[6];
    const float* Wl  = (const float*)d_in[7];
    const float* bl  = (const float*)d_in[8];
    float* out = (float*)d_out;

    const size_t st = (size_t)BB * HH;
    const size_t wS = (size_t)GG * HH;
    const size_t bS = (size_t)GG;

    const int gridA = (BB * TT) / AROWS;  // 9984, exact
    const int gridB = BB / 4;             // 8192, exact

    // Layer 0
    phaseA_kernel<<<gridA, 128>>>(x, Wih, bih, bhh, 0);
    phaseB_kernel<false><<<gridB, 128>>>(h0, c0, Whh, Wl, bl, out);
    // Layer 1
    phaseA_kernel<<<gridA, 128>>>(x, Wih + wS, bih + bS, bhh + bS, 1);
    phaseB_kernel<false><<<gridB, 128>>>(h0 + st, c0 + st, Whh + wS, Wl, bl, out);
    // Layer 2 (+ fused linear head)
    phaseA_kernel<<<gridA, 128>>>(x, Wih + 2 * wS, bih + 2 * bS, bhh + 2 * bS, 1);
    phaseB_kernel<true><<<gridB, 128>>>(h0 + 2 * st, c0 + 2 * st, Whh + 2 * wS, Wl, bl, out);
}

// round 6
// speedup vs baseline: 1.3656x; 1.3420x over previous
#include <cuda_runtime.h>

#define BB 32768
#define TT 78
#define HH 27
#define GG 108   // 4*H

// Scratch (device globals; accessed ONLY from device code)
static __device__ float4 g_xg[(size_t)BB * TT * HH];   // gate preactivations, gate-packed
static __device__ float  g_hbuf[(size_t)BB * TT * HH]; // inter-layer activations

__device__ __forceinline__ float sigf(float x) {
    return __fdividef(1.0f, 1.0f + __expf(-x));
}
__device__ __forceinline__ float tanhfast(float x) {
    return __fdividef(2.0f, 1.0f + __expf(-2.0f * x)) - 1.0f;
}

// ---------- packed f32x2 helpers ----------
__device__ __forceinline__ unsigned long long pack2(float lo, float hi) {
    unsigned long long r;
    asm("mov.b64 %0, {%1, %2};" : "=l"(r) : "f"(lo), "f"(hi));
    return r;
}
__device__ __forceinline__ void unpack2(unsigned long long v, float& lo, float& hi) {
    asm("mov.b64 {%0, %1}, %2;" : "=f"(lo), "=f"(hi) : "l"(v));
}
__device__ __forceinline__ unsigned long long fma2(unsigned long long a, unsigned long long b,
                                                   unsigned long long c) {
    unsigned long long d;
    asm("fma.rn.f32x2 %0, %1, %2, %3;" : "=l"(d) : "l"(a), "l"(b), "l"(c));
    return d;
}
__device__ __forceinline__ unsigned long long add2(unsigned long long a, unsigned long long b) {
    unsigned long long d;
    asm("add.rn.f32x2 %0, %1, %2;" : "=l"(d) : "l"(a), "l"(b));
    return d;
}

// ---------- cp.async helpers ----------
__device__ __forceinline__ void cpasync16(unsigned int saddr, const void* gaddr) {
    asm volatile("cp.async.cg.shared.global [%0], [%1], 16;" :: "r"(saddr), "l"(gaddr));
}
__device__ __forceinline__ void cpcommit() {
    asm volatile("cp.async.commit_group;" ::: "memory");
}
__device__ __forceinline__ void cpwait3() {
    asm volatile("cp.async.wait_group 3;" ::: "memory");
}

// ================= Phase A =================
// Weight-stationary: lane j owns gate column j (gate-pairs (i,f),(g,o) packed f32x2,
// weights in 108 registers). x staged coalesced into SMEM, read as uniform broadcast
// LDS.128. Each warp processes 32 row-pairs; output = direct coalesced float4 STG.

#define AROWS 256

__global__ void __launch_bounds__(128, 3)
phaseA_kernel(const float* __restrict__ xin,
              const float* __restrict__ Wih,
              const float* __restrict__ bih,
              const float* __restrict__ bhh,
              int src)                               // 0: xin, 1: g_hbuf (device-side select)
{
    __shared__ alignas(16) float xs[AROWS * 32];   // 32KB, row stride 32 (k=27 zeroed)

    const int tid = threadIdx.x;
    const int w   = tid >> 5;
    const int j   = tid & 31;
    const bool act = (j < HH);
    const int jj = act ? j : 0;

    // per-lane gate-pair weights in registers (k=27 pad = 0)
    unsigned long long wif[28], wgo[28];
#pragma unroll
    for (int k = 0; k < HH; ++k) {
        wif[k] = pack2(Wih[(0 * HH + jj) * HH + k], Wih[(1 * HH + jj) * HH + k]);
        wgo[k] = pack2(Wih[(2 * HH + jj) * HH + k], Wih[(3 * HH + jj) * HH + k]);
    }
    wif[27] = 0ull;
    wgo[27] = 0ull;
    const unsigned long long bif = pack2(bih[0 * HH + jj] + bhh[0 * HH + jj],
                                         bih[1 * HH + jj] + bhh[1 * HH + jj]);
    const unsigned long long bgo = pack2(bih[2 * HH + jj] + bhh[2 * HH + jj],
                                         bih[3 * HH + jj] + bhh[3 * HH + jj]);

    const float* in = (src == 0) ? xin : (const float*)g_hbuf;
    const size_t rowBase = (size_t)blockIdx.x * AROWS;
    const float* gsrc = in + rowBase * HH;

    // coalesced stage; zero the k=27 pad slot (read by q=6 chunk)
    for (int i = tid; i < AROWS * HH; i += 128) {
        int r = i / HH, k = i - r * HH;
        xs[r * 32 + k] = gsrc[i];
    }
    for (int r = tid; r < AROWS; r += 128) xs[r * 32 + HH] = 0.f;
    __syncthreads();

    // each warp: 32 row-pairs
#pragma unroll 1
    for (int mi = 0; mi < 32; ++mi) {
        const int rA = (w * 32 + mi) * 2;
        const float4* pa = reinterpret_cast<const float4*>(&xs[rA * 32]);
        const float4* pb = reinterpret_cast<const float4*>(&xs[(rA + 1) * 32]);

        unsigned long long aif = bif, ago = bgo;   // row A accumulators
        unsigned long long cif = bif, cgo = bgo;   // row B accumulators
#pragma unroll
        for (int q = 0; q < 7; ++q) {
            float4 xa = pa[q];
            float4 xb = pb[q];
            const int k = 4 * q;
            unsigned long long s;
            s = pack2(xa.x, xa.x); aif = fma2(s, wif[k + 0], aif); ago = fma2(s, wgo[k + 0], ago);
            s = pack2(xa.y, xa.y); aif = fma2(s, wif[k + 1], aif); ago = fma2(s, wgo[k + 1], ago);
            s = pack2(xa.z, xa.z); aif = fma2(s, wif[k + 2], aif); ago = fma2(s, wgo[k + 2], ago);
            s = pack2(xa.w, xa.w); aif = fma2(s, wif[k + 3], aif); ago = fma2(s, wgo[k + 3], ago);
            s = pack2(xb.x, xb.x); cif = fma2(s, wif[k + 0], cif); cgo = fma2(s, wgo[k + 0], cgo);
            s = pack2(xb.y, xb.y); cif = fma2(s, wif[k + 1], cif); cgo = fma2(s, wgo[k + 1], cgo);
            s = pack2(xb.z, xb.z); cif = fma2(s, wif[k + 2], cif); cgo = fma2(s, wgo[k + 2], cgo);
            s = pack2(xb.w, xb.w); cif = fma2(s, wif[k + 3], cif); cgo = fma2(s, wgo[k + 3], cgo);
        }

        if (act) {
            float v0, v1, v2, v3;
            unpack2(aif, v0, v1);
            unpack2(ago, v2, v3);
            g_xg[(rowBase + rA) * HH + j] = make_float4(v0, v1, v2, v3);
            unpack2(cif, v0, v1);
            unpack2(cgo, v2, v3);
            g_xg[(rowBase + rA + 1) * HH + j] = make_float4(v0, v1, v2, v3);
        }
    }
}

// ================= Phase B =================
// One warp per batch element; lane j owns gate pairs (i,f),(g,o) as f32x2, weights in regs.
// xg streamed via 4-stage cp.async ring (depth 3) to hide DRAM latency.
// h exchanged as splatted u64 pairs in SMEM; c in a register.

template<bool DOLIN>
__global__ void __launch_bounds__(128, 3)
phaseB_kernel(const float* __restrict__ h0,
              const float* __restrict__ c0,
              const float* __restrict__ Whh,
              const float* __restrict__ Wl,
              const float* __restrict__ bl,
              float* __restrict__ dout)
{
    __shared__ alignas(16) unsigned long long hs2[4][2][32]; // splatted h, ping-pong, pad 27..31
    __shared__ float whh_s[GG * HH];                          // staged Whh (11.7KB)
    __shared__ alignas(16) float4 xstage[4][4][32];           // [stage][warp][lane] 8KB
    __shared__ alignas(16) float hs_lin[4][2][32];            // plain h for linear head
    __shared__ alignas(16) float4 Wl4[32][8];
    __shared__ float bls[32];

    const int tid = threadIdx.x;
    const int w   = tid >> 5;
    const int j   = tid & 31;
    const bool act = (j < HH);
    const int jj = act ? j : 0;

    for (int i = tid; i < GG * HH; i += 128) whh_s[i] = Whh[i];   // coalesced
    if (DOLIN) {
        for (int i = tid; i < 32 * 7; i += 128) {
            int r = i / 7, q = i % 7;
            float4 v;
            v.x = (r < HH && 4 * q + 0 < HH) ? Wl[r * HH + 4 * q + 0] : 0.f;
            v.y = (r < HH && 4 * q + 1 < HH) ? Wl[r * HH + 4 * q + 1] : 0.f;
            v.z = (r < HH && 4 * q + 2 < HH) ? Wl[r * HH + 4 * q + 2] : 0.f;
            v.w = (r < HH && 4 * q + 3 < HH) ? Wl[r * HH + 4 * q + 3] : 0.f;
            Wl4[r][q] = v;
        }
        if (tid < 32) bls[tid] = (tid < HH) ? bl[tid] : 0.f;
    }
    __syncthreads();

    // gate-pair packed weights in regs (stride-729 LDS: conflict-free)
    unsigned long long wif[28], wgo[28];
#pragma unroll
    for (int k = 0; k < HH; ++k) {
        wif[k] = pack2(whh_s[(0 * HH + jj) * HH + k], whh_s[(1 * HH + jj) * HH + k]);
        wgo[k] = pack2(whh_s[(2 * HH + jj) * HH + k], whh_s[(3 * HH + jj) * HH + k]);
    }
    wif[27] = 0ull;
    wgo[27] = 0ull;

    const size_t b = (size_t)blockIdx.x * 4 + w;

    float c = act ? c0[b * HH + j] : 0.f;
    float hinit = act ? h0[b * HH + j] : 0.f;
    hs2[w][0][j] = pack2(hinit, hinit);
    hs2[w][1][j] = 0ull;
    if (DOLIN) { hs_lin[w][0][j] = hinit; hs_lin[w][1][j] = 0.f; }
    __syncwarp();

    const float4* xp = g_xg + b * (size_t)(TT * HH);
    float* op = (DOLIN ? dout : g_hbuf) + b * (size_t)(TT * HH);

    // cp.async ring: stage s holds xg for timestep t with t%4 == s
    const unsigned int xsbase =
        (unsigned int)__cvta_generic_to_shared(&xstage[0][w][j]);
    // stage stride = 4 warps * 32 lanes * 16B = 2048 bytes

    // prologue: issue t = 0,1,2
#pragma unroll
    for (int s = 0; s < 3; ++s) {
        if (act) cpasync16(xsbase + (unsigned)s * 2048u, xp + s * HH + j);
        cpcommit();
    }

    int p = 0;
    for (int t = 0; t < TT; ++t) {
        if (t + 3 < TT) {
            if (act) cpasync16(xsbase + (unsigned)((t + 3) & 3) * 2048u,
                               xp + (t + 3) * HH + j);
        }
        cpcommit();
        cpwait3();                       // stage t guaranteed complete
        float4 xv = xstage[t & 3][w][j];

        const ulonglong2* hp = reinterpret_cast<const ulonglong2*>(&hs2[w][p][0]);

        unsigned long long aif0 = pack2(xv.x, xv.y);
        unsigned long long ago0 = pack2(xv.z, xv.w);
        unsigned long long aif1 = 0ull, ago1 = 0ull;
#pragma unroll
        for (int q = 0; q < 14; ++q) {
            ulonglong2 h2 = hp[q];                 // uniform broadcast LDS.128
            aif0 = fma2(h2.x, wif[2 * q],     aif0);
            ago0 = fma2(h2.x, wgo[2 * q],     ago0);
            aif1 = fma2(h2.y, wif[2 * q + 1], aif1);
            ago1 = fma2(h2.y, wgo[2 * q + 1], ago1);
        }

        unsigned long long aif = add2(aif0, aif1);
        unsigned long long ago = add2(ago0, ago1);
        float ai, af, ag, ao;
        unpack2(aif, ai, af);
        unpack2(ago, ag, ao);

        float gi = sigf(ai);
        float gf = sigf(af);
        float gg = tanhfast(ag);
        float go = sigf(ao);
        c = fmaf(gf, c, gi * gg);
        float hn = go * tanhfast(c);

        if (act) {
            hs2[w][p ^ 1][j] = pack2(hn, hn);
            if (DOLIN) hs_lin[w][p ^ 1][j] = hn;
        }
        __syncwarp();

        if (DOLIN) {
            const float4* hq = reinterpret_cast<const float4*>(&hs_lin[w][p ^ 1][0]);
            float l0 = bls[jj], l1 = 0.f;
#pragma unroll
            for (int q = 0; q < 7; ++q) {
                float4 h4 = hq[q];
                float4 wl = Wl4[jj][q];
                l0 = fmaf(wl.x, h4.x, l0);
                l1 = fmaf(wl.y, h4.y, l1);
                l0 = fmaf(wl.z, h4.z, l0);
                l1 = fmaf(wl.w, h4.w, l1);
            }
            if (act) op[t * HH + j] = l0 + l1;
        } else {
            if (act) op[t * HH + j] = hn;
        }

        p ^= 1;
    }
}

// ================= host =================
extern "C" void kernel_launch(void* const* d_in, const int* in_sizes, int n_in,
                              void* d_out, int out_size)
{
    const float* x   = (const float*)d_in[0];
    const float* h0  = (const float*)d_in[1];
    const float* c0  = (const float*)d_in[2];
    const float* Wih = (const float*)d_in[3];
    const float* Whh = (const float*)d_in[4];
    const float* bih = (const float*)d_in[5];
    const float* bhh = (const float*)d_in[6];
    const float* Wl  = (const float*)d_in[7];
    const float* bl  = (const float*)d_in[8];
    float* out = (float*)d_out;

    const size_t st = (size_t)BB * HH;
    const size_t wS = (size_t)GG * HH;
    const size_t bS = (size_t)GG;

    const int gridA = (BB * TT) / AROWS;  // 9984, exact
    const int gridB = BB / 4;             // 8192, exact

    // Layer 0
    phaseA_kernel<<<gridA, 128>>>(x, Wih, bih, bhh, 0);
    phaseB_kernel<false><<<gridB, 128>>>(h0, c0, Whh, Wl, bl, out);
    // Layer 1
    phaseA_kernel<<<gridA, 128>>>(x, Wih + wS, bih + bS, bhh + bS, 1);
    phaseB_kernel<false><<<gridB, 128>>>(h0 + st, c0 + st, Whh + wS, Wl, bl, out);
    // Layer 2 (+ fused linear head)
    phaseA_kernel<<<gridA, 128>>>(x, Wih + 2 * wS, bih + 2 * bS, bhh + 2 * bS, 1);
    phaseB_kernel<true><<<gridB, 128>>>(h0 + 2 * st, c0 + 2 * st, Whh + 2 * wS, Wl, bl, out);
}

// round 7
// speedup vs baseline: 1.6914x; 1.2386x over previous
#include <cuda_runtime.h>

#define BB 32768
#define TT 78
#define HH 27
#define GG 108   // 4*H

// Scratch (device globals; accessed ONLY from device code)
static __device__ float4 g_xg[(size_t)BB * TT * HH];   // gate preactivations, gate-packed
static __device__ float  g_hbuf[(size_t)BB * TT * HH]; // inter-layer activations

__device__ __forceinline__ float sigf(float x) {
    return __fdividef(1.0f, 1.0f + __expf(-x));
}
__device__ __forceinline__ float tanhfast(float x) {
    return __fdividef(2.0f, 1.0f + __expf(-2.0f * x)) - 1.0f;
}

// ---------- packed f32x2 helpers ----------
__device__ __forceinline__ unsigned long long pack2(float lo, float hi) {
    unsigned long long r;
    asm("mov.b64 %0, {%1, %2};" : "=l"(r) : "f"(lo), "f"(hi));
    return r;
}
__device__ __forceinline__ void unpack2(unsigned long long v, float& lo, float& hi) {
    asm("mov.b64 {%0, %1}, %2;" : "=f"(lo), "=f"(hi) : "l"(v));
}
__device__ __forceinline__ unsigned long long fma2(unsigned long long a, unsigned long long b,
                                                   unsigned long long c) {
    unsigned long long d;
    asm("fma.rn.f32x2 %0, %1, %2, %3;" : "=l"(d) : "l"(a), "l"(b), "l"(c));
    return d;
}

// ---------- cp.async helpers ----------
__device__ __forceinline__ void cpasync16(unsigned int saddr, const void* gaddr) {
    asm volatile("cp.async.cg.shared.global [%0], [%1], 16;" :: "r"(saddr), "l"(gaddr));
}
__device__ __forceinline__ void cpcommit() {
    asm volatile("cp.async.commit_group;" ::: "memory");
}
__device__ __forceinline__ void cpwait3() {
    asm volatile("cp.async.wait_group 3;" ::: "memory");
}

// ================= Phase A =================
// Weight-stationary: lane j owns gate column j (gate-pairs (i,f),(g,o) packed f32x2,
// weights in 108 registers). x staged coalesced into SMEM, read as uniform broadcast
// LDS.128. Output staged per-warp in SMEM, flushed with contiguous coalesced STG.128.

#define AROWS 256

__global__ void __launch_bounds__(128, 3)
phaseA_kernel(const float* __restrict__ xin,
              const float* __restrict__ Wih,
              const float* __restrict__ bih,
              const float* __restrict__ bhh,
              int src)                               // 0: xin, 1: g_hbuf (device-side select)
{
    __shared__ alignas(16) float xs[AROWS * 32];     // 32KB, row stride 32 (k=27 zeroed)
    __shared__ alignas(16) float4 os[4][56];         // per-warp output stage (54 used)

    const int tid = threadIdx.x;
    const int w   = tid >> 5;
    const int j   = tid & 31;
    const bool act = (j < HH);
    const int jj = act ? j : 0;

    // per-lane gate-pair weights in registers (k=27 pad = 0)
    unsigned long long wif[28], wgo[28];
#pragma unroll
    for (int k = 0; k < HH; ++k) {
        wif[k] = pack2(Wih[(0 * HH + jj) * HH + k], Wih[(1 * HH + jj) * HH + k]);
        wgo[k] = pack2(Wih[(2 * HH + jj) * HH + k], Wih[(3 * HH + jj) * HH + k]);
    }
    wif[27] = 0ull;
    wgo[27] = 0ull;
    const unsigned long long bif = pack2(bih[0 * HH + jj] + bhh[0 * HH + jj],
                                         bih[1 * HH + jj] + bhh[1 * HH + jj]);
    const unsigned long long bgo = pack2(bih[2 * HH + jj] + bhh[2 * HH + jj],
                                         bih[3 * HH + jj] + bhh[3 * HH + jj]);

    const float* in = (src == 0) ? xin : (const float*)g_hbuf;
    const size_t rowBase = (size_t)blockIdx.x * AROWS;
    const float* gsrc = in + rowBase * HH;

    // coalesced stage; zero the k=27 pad slot
    for (int i = tid; i < AROWS * HH; i += 128) {
        int r = i / HH, k = i - r * HH;
        xs[r * 32 + k] = gsrc[i];
    }
    for (int r = tid; r < AROWS; r += 128) xs[r * 32 + HH] = 0.f;
    __syncthreads();

    // each warp: 32 row-pairs
#pragma unroll 1
    for (int mi = 0; mi < 32; ++mi) {
        const int rA = (w * 32 + mi) * 2;
        const float4* pa = reinterpret_cast<const float4*>(&xs[rA * 32]);
        const float4* pb = reinterpret_cast<const float4*>(&xs[(rA + 1) * 32]);

        unsigned long long aif = bif, ago = bgo;   // row A accumulators
        unsigned long long cif = bif, cgo = bgo;   // row B accumulators
#pragma unroll
        for (int q = 0; q < 7; ++q) {
            float4 xa = pa[q];
            float4 xb = pb[q];
            const int k = 4 * q;
            unsigned long long s;
            s = pack2(xa.x, xa.x); aif = fma2(s, wif[k + 0], aif); ago = fma2(s, wgo[k + 0], ago);
            s = pack2(xa.y, xa.y); aif = fma2(s, wif[k + 1], aif); ago = fma2(s, wgo[k + 1], ago);
            s = pack2(xa.z, xa.z); aif = fma2(s, wif[k + 2], aif); ago = fma2(s, wgo[k + 2], ago);
            s = pack2(xa.w, xa.w); aif = fma2(s, wif[k + 3], aif); ago = fma2(s, wgo[k + 3], ago);
            s = pack2(xb.x, xb.x); cif = fma2(s, wif[k + 0], cif); cgo = fma2(s, wgo[k + 0], cgo);
            s = pack2(xb.y, xb.y); cif = fma2(s, wif[k + 1], cif); cgo = fma2(s, wgo[k + 1], cgo);
            s = pack2(xb.z, xb.z); cif = fma2(s, wif[k + 2], cif); cgo = fma2(s, wgo[k + 2], cgo);
            s = pack2(xb.w, xb.w); cif = fma2(s, wif[k + 3], cif); cgo = fma2(s, wgo[k + 3], cgo);
        }

        // stage to SMEM: element e<27 = row A col e; e in [27,54) = row B col e-27
        if (act) {
            float v0, v1, v2, v3;
            unpack2(aif, v0, v1);
            unpack2(ago, v2, v3);
            os[w][j] = make_float4(v0, v1, v2, v3);
            unpack2(cif, v0, v1);
            unpack2(cgo, v2, v3);
            os[w][HH + j] = make_float4(v0, v1, v2, v3);
        }
        __syncwarp();

        // flush: rows A,B are adjacent in gmem -> 54 contiguous float4s
        float4* gdst = g_xg + (rowBase + rA) * HH;
        gdst[j] = os[w][j];                       // e = 0..31
        if (j < 2 * HH - 32) gdst[32 + j] = os[w][32 + j];   // e = 32..53
        __syncwarp();
    }
}

// ================= Phase B =================
// One warp per TWO batch elements (weights shared in regs; 2 independent recurrence
// chains give 2x ILP). Lane j owns gate pairs (i,f),(g,o) as f32x2.
// xg streamed via 4-stage cp.async ring (depth 3). h exchanged as splatted u64 in SMEM.

template<bool DOLIN>
__global__ void __launch_bounds__(128, 3)
phaseB_kernel(const float* __restrict__ h0,
              const float* __restrict__ c0,
              const float* __restrict__ Whh,
              const float* __restrict__ Wl,
              const float* __restrict__ bl,
              float* __restrict__ dout)
{
    __shared__ alignas(16) unsigned long long hs2[4][2][2][32]; // [warp][elem][ping][lane]
    __shared__ float whh_s[GG * HH];                             // staged Whh (11.7KB)
    __shared__ alignas(16) float4 xstage[4][4][2][32];           // [stage][warp][elem][lane] 16KB
    __shared__ alignas(16) float hs_lin[4][2][2][32];            // plain h for linear head
    __shared__ alignas(16) float4 Wl4[32][8];
    __shared__ float bls[32];

    const int tid = threadIdx.x;
    const int w   = tid >> 5;
    const int j   = tid & 31;
    const bool act = (j < HH);
    const int jj = act ? j : 0;

    for (int i = tid; i < GG * HH; i += 128) whh_s[i] = Whh[i];   // coalesced
    if (DOLIN) {
        for (int i = tid; i < 32 * 7; i += 128) {
            int r = i / 7, q = i % 7;
            float4 v;
            v.x = (r < HH && 4 * q + 0 < HH) ? Wl[r * HH + 4 * q + 0] : 0.f;
            v.y = (r < HH && 4 * q + 1 < HH) ? Wl[r * HH + 4 * q + 1] : 0.f;
            v.z = (r < HH && 4 * q + 2 < HH) ? Wl[r * HH + 4 * q + 2] : 0.f;
            v.w = (r < HH && 4 * q + 3 < HH) ? Wl[r * HH + 4 * q + 3] : 0.f;
            Wl4[r][q] = v;
        }
        if (tid < 32) bls[tid] = (tid < HH) ? bl[tid] : 0.f;
    }
    __syncthreads();

    // gate-pair packed weights in regs
    unsigned long long wif[28], wgo[28];
#pragma unroll
    for (int k = 0; k < HH; ++k) {
        wif[k] = pack2(whh_s[(0 * HH + jj) * HH + k], whh_s[(1 * HH + jj) * HH + k]);
        wgo[k] = pack2(whh_s[(2 * HH + jj) * HH + k], whh_s[(3 * HH + jj) * HH + k]);
    }
    wif[27] = 0ull;
    wgo[27] = 0ull;

    const size_t b0 = (size_t)blockIdx.x * 8 + w * 2;
    const size_t b1 = b0 + 1;

    float cA = act ? c0[b0 * HH + j] : 0.f;
    float cB = act ? c0[b1 * HH + j] : 0.f;
    float hA = act ? h0[b0 * HH + j] : 0.f;
    float hB = act ? h0[b1 * HH + j] : 0.f;
    hs2[w][0][0][j] = pack2(hA, hA);
    hs2[w][1][0][j] = pack2(hB, hB);
    hs2[w][0][1][j] = 0ull;
    hs2[w][1][1][j] = 0ull;
    if (DOLIN) {
        hs_lin[w][0][0][j] = hA; hs_lin[w][1][0][j] = hB;
        hs_lin[w][0][1][j] = 0.f; hs_lin[w][1][1][j] = 0.f;
    }
    __syncwarp();

    const float4* xp0 = g_xg + b0 * (size_t)(TT * HH);
    const float4* xp1 = g_xg + b1 * (size_t)(TT * HH);
    float* op0 = (DOLIN ? dout : g_hbuf) + b0 * (size_t)(TT * HH);
    float* op1 = (DOLIN ? dout : g_hbuf) + b1 * (size_t)(TT * HH);

    // cp.async ring: stage stride 4096B, elem stride 512B
    const unsigned int xsbase =
        (unsigned int)__cvta_generic_to_shared(&xstage[0][w][0][j]);

#pragma unroll
    for (int s = 0; s < 3; ++s) {
        if (act) {
            cpasync16(xsbase + (unsigned)s * 4096u,        xp0 + s * HH + j);
            cpasync16(xsbase + (unsigned)s * 4096u + 512u, xp1 + s * HH + j);
        }
        cpcommit();
    }

    int p = 0;
    for (int t = 0; t < TT; ++t) {
        if (t + 3 < TT && act) {
            unsigned int sa = xsbase + (unsigned)((t + 3) & 3) * 4096u;
            cpasync16(sa,        xp0 + (t + 3) * HH + j);
            cpasync16(sa + 512u, xp1 + (t + 3) * HH + j);
        }
        cpcommit();
        cpwait3();
        float4 xvA = xstage[t & 3][w][0][j];
        float4 xvB = xstage[t & 3][w][1][j];

        const ulonglong2* hpA = reinterpret_cast<const ulonglong2*>(&hs2[w][0][p][0]);
        const ulonglong2* hpB = reinterpret_cast<const ulonglong2*>(&hs2[w][1][p][0]);

        unsigned long long aifA = pack2(xvA.x, xvA.y);
        unsigned long long agoA = pack2(xvA.z, xvA.w);
        unsigned long long aifB = pack2(xvB.x, xvB.y);
        unsigned long long agoB = pack2(xvB.z, xvB.w);
#pragma unroll
        for (int q = 0; q < 14; ++q) {
            ulonglong2 h2A = hpA[q];               // uniform broadcast LDS.128
            ulonglong2 h2B = hpB[q];
            aifA = fma2(h2A.x, wif[2 * q],     aifA);
            agoA = fma2(h2A.x, wgo[2 * q],     agoA);
            aifB = fma2(h2B.x, wif[2 * q],     aifB);
            agoB = fma2(h2B.x, wgo[2 * q],     agoB);
            aifA = fma2(h2A.y, wif[2 * q + 1], aifA);
            agoA = fma2(h2A.y, wgo[2 * q + 1], agoA);
            aifB = fma2(h2B.y, wif[2 * q + 1], aifB);
            agoB = fma2(h2B.y, wgo[2 * q + 1], agoB);
        }

        float ai, af, ag, ao;
        unpack2(aifA, ai, af);
        unpack2(agoA, ag, ao);
        float giA = sigf(ai), gfA = sigf(af), ggA = tanhfast(ag), goA = sigf(ao);
        cA = fmaf(gfA, cA, giA * ggA);
        float hnA = goA * tanhfast(cA);

        unpack2(aifB, ai, af);
        unpack2(agoB, ag, ao);
        float giB = sigf(ai), gfB = sigf(af), ggB = tanhfast(ag), goB = sigf(ao);
        cB = fmaf(gfB, cB, giB * ggB);
        float hnB = goB * tanhfast(cB);

        if (act) {
            hs2[w][0][p ^ 1][j] = pack2(hnA, hnA);
            hs2[w][1][p ^ 1][j] = pack2(hnB, hnB);
            if (DOLIN) {
                hs_lin[w][0][p ^ 1][j] = hnA;
                hs_lin[w][1][p ^ 1][j] = hnB;
            }
        }
        __syncwarp();

        if (DOLIN) {
            const float4* hqA = reinterpret_cast<const float4*>(&hs_lin[w][0][p ^ 1][0]);
            const float4* hqB = reinterpret_cast<const float4*>(&hs_lin[w][1][p ^ 1][0]);
            float lA0 = bls[jj], lA1 = 0.f, lB0 = bls[jj], lB1 = 0.f;
#pragma unroll
            for (int q = 0; q < 7; ++q) {
                float4 h4A = hqA[q];
                float4 h4B = hqB[q];
                float4 wl = Wl4[jj][q];
                lA0 = fmaf(wl.x, h4A.x, lA0);
                lA1 = fmaf(wl.y, h4A.y, lA1);
                lA0 = fmaf(wl.z, h4A.z, lA0);
                lA1 = fmaf(wl.w, h4A.w, lA1);
                lB0 = fmaf(wl.x, h4B.x, lB0);
                lB1 = fmaf(wl.y, h4B.y, lB1);
                lB0 = fmaf(wl.z, h4B.z, lB0);
                lB1 = fmaf(wl.w, h4B.w, lB1);
            }
            if (act) {
                op0[t * HH + j] = lA0 + lA1;
                op1[t * HH + j] = lB0 + lB1;
            }
        } else {
            if (act) {
                op0[t * HH + j] = hnA;
                op1[t * HH + j] = hnB;
            }
        }

        p ^= 1;
    }
}

// ================= host =================
extern "C" void kernel_launch(void* const* d_in, const int* in_sizes, int n_in,
                              void* d_out, int out_size)
{
    const float* x   = (const float*)d_in[0];
    const float* h0  = (const float*)d_in[1];
    const float* c0  = (const float*)d_in[2];
    const float* Wih = (const float*)d_in[3];
    const float* Whh = (const float*)d_in[4];
    const float* bih = (const float*)d_in[5];
    const float* bhh = (const float*)d_in[6];
    const float* Wl  = (const float*)d_in[7];
    const float* bl  = (const float*)d_in[8];
    float* out = (float*)d_out;

    const size_t st = (size_t)BB * HH;
    const size_t wS = (size_t)GG * HH;
    const size_t bS = (size_t)GG;

    const int gridA = (BB * TT) / AROWS;  // 9984, exact
    const int gridB = BB / 8;             // 4096, exact

    // Layer 0
    phaseA_kernel<<<gridA, 128>>>(x, Wih, bih, bhh, 0);
    phaseB_kernel<false><<<gridB, 128>>>(h0, c0, Whh, Wl, bl, out);
    // Layer 1
    phaseA_kernel<<<gridA, 128>>>(x, Wih + wS, bih + bS, bhh + bS, 1);
    phaseB_kernel<false><<<gridB, 128>>>(h0 + st, c0 + st, Whh + wS, Wl, bl, out);
    // Layer 2 (+ fused linear head)
    phaseA_kernel<<<gridA, 128>>>(x, Wih + 2 * wS, bih + 2 * bS, bhh + 2 * bS, 1);
    phaseB_kernel<true><<<gridB, 128>>>(h0 + 2 * st, c0 + 2 * st, Whh + 2 * wS, Wl, bl, out);
}

// round 8
// speedup vs baseline: 1.7150x; 1.0139x over previous
#include <cuda_runtime.h>

#define BB 32768
#define TT 78
#define HH 27
#define GG 108   // 4*H

// Ping-pong xg buffers (device globals; accessed ONLY from device code)
static __device__ float4 g_xg0[(size_t)BB * TT * HH];
static __device__ float4 g_xg1[(size_t)BB * TT * HH];

__device__ __forceinline__ float sigf(float x) {
    return __fdividef(1.0f, 1.0f + __expf(-x));
}
__device__ __forceinline__ float tanhfast(float x) {
    return __fdividef(2.0f, 1.0f + __expf(-2.0f * x)) - 1.0f;
}

// ---------- packed f32x2 helpers ----------
__device__ __forceinline__ unsigned long long pack2(float lo, float hi) {
    unsigned long long r;
    asm("mov.b64 %0, {%1, %2};" : "=l"(r) : "f"(lo), "f"(hi));
    return r;
}
__device__ __forceinline__ void unpack2(unsigned long long v, float& lo, float& hi) {
    asm("mov.b64 {%0, %1}, %2;" : "=f"(lo), "=f"(hi) : "l"(v));
}
__device__ __forceinline__ unsigned long long fma2(unsigned long long a, unsigned long long b,
                                                   unsigned long long c) {
    unsigned long long d;
    asm("fma.rn.f32x2 %0, %1, %2, %3;" : "=l"(d) : "l"(a), "l"(b), "l"(c));
    return d;
}

// ---------- cp.async helpers ----------
__device__ __forceinline__ void cpasync16(unsigned int saddr, const void* gaddr) {
    asm volatile("cp.async.cg.shared.global [%0], [%1], 16;" :: "r"(saddr), "l"(gaddr));
}
__device__ __forceinline__ void cpcommit() {
    asm volatile("cp.async.commit_group;" ::: "memory");
}
__device__ __forceinline__ void cpwait3() {
    asm volatile("cp.async.wait_group 3;" ::: "memory");
}
__device__ __forceinline__ void barsync(int id, int cnt) {
    asm volatile("bar.sync %0, %1;" :: "r"(id), "r"(cnt) : "memory");
}

// ================= Phase A (layer 0 only): xg0 = x @ Wih0^T + b =================
#define AROWS 256

__global__ void __launch_bounds__(128, 3)
phaseA_kernel(const float* __restrict__ xin,
              const float* __restrict__ Wih,
              const float* __restrict__ bih,
              const float* __restrict__ bhh)
{
    __shared__ alignas(16) float xs[AROWS * 32];     // row stride 32 (k=27 zeroed)
    __shared__ alignas(16) float4 os[4][56];         // per-warp output stage

    const int tid = threadIdx.x;
    const int w   = tid >> 5;
    const int j   = tid & 31;
    const bool act = (j < HH);
    const int jj = act ? j : 0;

    unsigned long long wif[28], wgo[28];
#pragma unroll
    for (int k = 0; k < HH; ++k) {
        wif[k] = pack2(Wih[(0 * HH + jj) * HH + k], Wih[(1 * HH + jj) * HH + k]);
        wgo[k] = pack2(Wih[(2 * HH + jj) * HH + k], Wih[(3 * HH + jj) * HH + k]);
    }
    wif[27] = 0ull;
    wgo[27] = 0ull;
    const unsigned long long bif = pack2(bih[0 * HH + jj] + bhh[0 * HH + jj],
                                         bih[1 * HH + jj] + bhh[1 * HH + jj]);
    const unsigned long long bgo = pack2(bih[2 * HH + jj] + bhh[2 * HH + jj],
                                         bih[3 * HH + jj] + bhh[3 * HH + jj]);

    const size_t rowBase = (size_t)blockIdx.x * AROWS;
    const float* gsrc = xin + rowBase * HH;

    for (int i = tid; i < AROWS * HH; i += 128) {
        int r = i / HH, k = i - r * HH;
        xs[r * 32 + k] = gsrc[i];
    }
    for (int r = tid; r < AROWS; r += 128) xs[r * 32 + HH] = 0.f;
    __syncthreads();

#pragma unroll 1
    for (int mi = 0; mi < 32; ++mi) {
        const int rA = (w * 32 + mi) * 2;
        const float4* pa = reinterpret_cast<const float4*>(&xs[rA * 32]);
        const float4* pb = reinterpret_cast<const float4*>(&xs[(rA + 1) * 32]);

        unsigned long long aif = bif, ago = bgo;
        unsigned long long cif = bif, cgo = bgo;
#pragma unroll
        for (int q = 0; q < 7; ++q) {
            float4 xa = pa[q];
            float4 xb = pb[q];
            const int k = 4 * q;
            unsigned long long s;
            s = pack2(xa.x, xa.x); aif = fma2(s, wif[k + 0], aif); ago = fma2(s, wgo[k + 0], ago);
            s = pack2(xa.y, xa.y); aif = fma2(s, wif[k + 1], aif); ago = fma2(s, wgo[k + 1], ago);
            s = pack2(xa.z, xa.z); aif = fma2(s, wif[k + 2], aif); ago = fma2(s, wgo[k + 2], ago);
            s = pack2(xa.w, xa.w); aif = fma2(s, wif[k + 3], aif); ago = fma2(s, wgo[k + 3], ago);
            s = pack2(xb.x, xb.x); cif = fma2(s, wif[k + 0], cif); cgo = fma2(s, wgo[k + 0], cgo);
            s = pack2(xb.y, xb.y); cif = fma2(s, wif[k + 1], cif); cgo = fma2(s, wgo[k + 1], cgo);
            s = pack2(xb.z, xb.z); cif = fma2(s, wif[k + 2], cif); cgo = fma2(s, wgo[k + 2], cgo);
            s = pack2(xb.w, xb.w); cif = fma2(s, wif[k + 3], cif); cgo = fma2(s, wgo[k + 3], cgo);
        }

        if (act) {
            float v0, v1, v2, v3;
            unpack2(aif, v0, v1);
            unpack2(ago, v2, v3);
            os[w][j] = make_float4(v0, v1, v2, v3);
            unpack2(cif, v0, v1);
            unpack2(cgo, v2, v3);
            os[w][HH + j] = make_float4(v0, v1, v2, v3);
        }
        __syncwarp();

        float4* gdst = g_xg0 + (rowBase + rA) * HH;
        gdst[j] = os[w][j];
        if (j < 2 * HH - 32) gdst[32 + j] = os[w][32 + j];
        __syncwarp();
    }
}

// ================= Fused: recurrence of layer l (warps 0,1) + feed-forward of
// layer l+1 (warps 2,3). Pair (w, w+2) shares 2 batch elements via SMEM h-splats,
// synchronized by one named barrier per timestep (pipeline depth 1).

__global__ void __launch_bounds__(128, 3)
fusedB_kernel(const float* __restrict__ h0,
              const float* __restrict__ c0,
              const float* __restrict__ WhhL,   // layer l
              const float* __restrict__ WihN,   // layer l+1
              const float* __restrict__ bihN,
              const float* __restrict__ bhhN,
              int dir)                           // 0: xg0 -> xg1 ; 1: xg1 -> xg0
{
    __shared__ float whh_s[GG * HH];
    __shared__ float wih_s[GG * HH];
    __shared__ alignas(16) unsigned long long hs2[2][2][2][32]; // [pid][elem][slot][lane]
    __shared__ alignas(16) float4 xstage[4][2][2][32];          // [stage][pid][elem][lane]

    const int tid = threadIdx.x;
    const int w   = tid >> 5;
    const int j   = tid & 31;
    const bool act = (j < HH);
    const int jj = act ? j : 0;
    const int pid = w & 1;
    const bool isRec = (w < 2);

    for (int i = tid; i < GG * HH; i += 128) {
        whh_s[i] = WhhL[i];
        wih_s[i] = WihN[i];
    }
    __syncthreads();

    // role-specific weights in registers (both paths: 56 u64)
    const float* wsrc = isRec ? whh_s : wih_s;
    unsigned long long wif[28], wgo[28];
#pragma unroll
    for (int k = 0; k < HH; ++k) {
        wif[k] = pack2(wsrc[(0 * HH + jj) * HH + k], wsrc[(1 * HH + jj) * HH + k]);
        wgo[k] = pack2(wsrc[(2 * HH + jj) * HH + k], wsrc[(3 * HH + jj) * HH + k]);
    }
    wif[27] = 0ull;
    wgo[27] = 0ull;

    const float4* xsrc = (dir == 0) ? g_xg0 : g_xg1;
    float4*       xdst = (dir == 0) ? g_xg1 : g_xg0;

    const size_t b0 = (size_t)blockIdx.x * 4 + pid * 2;
    const size_t b1 = b0 + 1;

    if (isRec) {
        float cA = act ? c0[b0 * HH + j] : 0.f;
        float cB = act ? c0[b1 * HH + j] : 0.f;
        float hA = act ? h0[b0 * HH + j] : 0.f;
        float hB = act ? h0[b1 * HH + j] : 0.f;
        hs2[pid][0][0][j] = pack2(hA, hA);
        hs2[pid][1][0][j] = pack2(hB, hB);
        __syncwarp();

        const float4* xp0 = xsrc + b0 * (size_t)(TT * HH);
        const float4* xp1 = xsrc + b1 * (size_t)(TT * HH);
        const unsigned int xsbase =
            (unsigned int)__cvta_generic_to_shared(&xstage[0][pid][0][j]);
        // strides: stage 2048B, elem 512B

#pragma unroll
        for (int s = 0; s < 3; ++s) {
            if (act) {
                cpasync16(xsbase + (unsigned)s * 2048u,        xp0 + s * HH + j);
                cpasync16(xsbase + (unsigned)s * 2048u + 512u, xp1 + s * HH + j);
            }
            cpcommit();
        }

        int p = 0;
        for (int t = 0; t < TT; ++t) {
            if (t + 3 < TT && act) {
                unsigned int sa = xsbase + (unsigned)((t + 3) & 3) * 2048u;
                cpasync16(sa,        xp0 + (t + 3) * HH + j);
                cpasync16(sa + 512u, xp1 + (t + 3) * HH + j);
            }
            cpcommit();
            cpwait3();
            float4 xvA = xstage[t & 3][pid][0][j];
            float4 xvB = xstage[t & 3][pid][1][j];

            const ulonglong2* hpA = reinterpret_cast<const ulonglong2*>(&hs2[pid][0][p][0]);
            const ulonglong2* hpB = reinterpret_cast<const ulonglong2*>(&hs2[pid][1][p][0]);

            unsigned long long aifA = pack2(xvA.x, xvA.y);
            unsigned long long agoA = pack2(xvA.z, xvA.w);
            unsigned long long aifB = pack2(xvB.x, xvB.y);
            unsigned long long agoB = pack2(xvB.z, xvB.w);
#pragma unroll
            for (int q = 0; q < 14; ++q) {
                ulonglong2 h2A = hpA[q];
                ulonglong2 h2B = hpB[q];
                aifA = fma2(h2A.x, wif[2 * q],     aifA);
                agoA = fma2(h2A.x, wgo[2 * q],     agoA);
                aifB = fma2(h2B.x, wif[2 * q],     aifB);
                agoB = fma2(h2B.x, wgo[2 * q],     agoB);
                aifA = fma2(h2A.y, wif[2 * q + 1], aifA);
                agoA = fma2(h2A.y, wgo[2 * q + 1], agoA);
                aifB = fma2(h2B.y, wif[2 * q + 1], aifB);
                agoB = fma2(h2B.y, wgo[2 * q + 1], agoB);
            }

            float ai, af, ag, ao;
            unpack2(aifA, ai, af);
            unpack2(agoA, ag, ao);
            float giA = sigf(ai), gfA = sigf(af), ggA = tanhfast(ag), goA = sigf(ao);
            cA = fmaf(gfA, cA, giA * ggA);
            float hnA = goA * tanhfast(cA);

            unpack2(aifB, ai, af);
            unpack2(agoB, ag, ao);
            float giB = sigf(ai), gfB = sigf(af), ggB = tanhfast(ag), goB = sigf(ao);
            cB = fmaf(gfB, cB, giB * ggB);
            float hnB = goB * tanhfast(cB);

            if (act) {
                hs2[pid][0][p ^ 1][j] = pack2(hnA, hnA);
                hs2[pid][1][p ^ 1][j] = pack2(hnB, hnB);
            }
            barsync(2 + pid, 64);   // publish h_t to FF partner
            p ^= 1;
        }
    } else {
        const unsigned long long bif = pack2(bihN[0 * HH + jj] + bhhN[0 * HH + jj],
                                             bihN[1 * HH + jj] + bhhN[1 * HH + jj]);
        const unsigned long long bgo = pack2(bihN[2 * HH + jj] + bhhN[2 * HH + jj],
                                             bihN[3 * HH + jj] + bhhN[3 * HH + jj]);
        float4* op0 = xdst + b0 * (size_t)(TT * HH);
        float4* op1 = xdst + b1 * (size_t)(TT * HH);

        int p = 0;
        for (int t = 0; t < TT; ++t) {
            barsync(2 + pid, 64);   // wait for h_t

            const ulonglong2* hpA = reinterpret_cast<const ulonglong2*>(&hs2[pid][0][p ^ 1][0]);
            const ulonglong2* hpB = reinterpret_cast<const ulonglong2*>(&hs2[pid][1][p ^ 1][0]);

            unsigned long long aifA = bif, agoA = bgo;
            unsigned long long aifB = bif, agoB = bgo;
#pragma unroll
            for (int q = 0; q < 14; ++q) {
                ulonglong2 h2A = hpA[q];
                ulonglong2 h2B = hpB[q];
                aifA = fma2(h2A.x, wif[2 * q],     aifA);
                agoA = fma2(h2A.x, wgo[2 * q],     agoA);
                aifB = fma2(h2B.x, wif[2 * q],     aifB);
                agoB = fma2(h2B.x, wgo[2 * q],     agoB);
                aifA = fma2(h2A.y, wif[2 * q + 1], aifA);
                agoA = fma2(h2A.y, wgo[2 * q + 1], agoA);
                aifB = fma2(h2B.y, wif[2 * q + 1], aifB);
                agoB = fma2(h2B.y, wgo[2 * q + 1], agoB);
            }

            if (act) {
                float v0, v1, v2, v3;
                unpack2(aifA, v0, v1);
                unpack2(agoA, v2, v3);
                op0[t * HH + j] = make_float4(v0, v1, v2, v3);
                unpack2(aifB, v0, v1);
                unpack2(agoB, v2, v3);
                op1[t * HH + j] = make_float4(v0, v1, v2, v3);
            }
            p ^= 1;
        }
    }
}

// ================= Final layer: recurrence + fused linear head (reads g_xg0) ======

__global__ void __launch_bounds__(128, 3)
phaseB_lin_kernel(const float* __restrict__ h0,
                  const float* __restrict__ c0,
                  const float* __restrict__ Whh,
                  const float* __restrict__ Wl,
                  const float* __restrict__ bl,
                  float* __restrict__ dout)
{
    __shared__ alignas(16) unsigned long long hs2[4][2][2][32];
    __shared__ float whh_s[GG * HH];
    __shared__ alignas(16) float4 xstage[4][4][2][32];
    __shared__ alignas(16) float hs_lin[4][2][2][32];
    __shared__ alignas(16) float4 Wl4[32][8];
    __shared__ float bls[32];

    const int tid = threadIdx.x;
    const int w   = tid >> 5;
    const int j   = tid & 31;
    const bool act = (j < HH);
    const int jj = act ? j : 0;

    for (int i = tid; i < GG * HH; i += 128) whh_s[i] = Whh[i];
    for (int i = tid; i < 32 * 7; i += 128) {
        int r = i / 7, q = i % 7;
        float4 v;
        v.x = (r < HH && 4 * q + 0 < HH) ? Wl[r * HH + 4 * q + 0] : 0.f;
        v.y = (r < HH && 4 * q + 1 < HH) ? Wl[r * HH + 4 * q + 1] : 0.f;
        v.z = (r < HH && 4 * q + 2 < HH) ? Wl[r * HH + 4 * q + 2] : 0.f;
        v.w = (r < HH && 4 * q + 3 < HH) ? Wl[r * HH + 4 * q + 3] : 0.f;
        Wl4[r][q] = v;
    }
    if (tid < 32) bls[tid] = (tid < HH) ? bl[tid] : 0.f;
    __syncthreads();

    unsigned long long wif[28], wgo[28];
#pragma unroll
    for (int k = 0; k < HH; ++k) {
        wif[k] = pack2(whh_s[(0 * HH + jj) * HH + k], whh_s[(1 * HH + jj) * HH + k]);
        wgo[k] = pack2(whh_s[(2 * HH + jj) * HH + k], whh_s[(3 * HH + jj) * HH + k]);
    }
    wif[27] = 0ull;
    wgo[27] = 0ull;

    const size_t b0 = (size_t)blockIdx.x * 8 + w * 2;
    const size_t b1 = b0 + 1;

    float cA = act ? c0[b0 * HH + j] : 0.f;
    float cB = act ? c0[b1 * HH + j] : 0.f;
    float hA = act ? h0[b0 * HH + j] : 0.f;
    float hB = act ? h0[b1 * HH + j] : 0.f;
    hs2[w][0][0][j] = pack2(hA, hA);
    hs2[w][1][0][j] = pack2(hB, hB);
    hs_lin[w][0][0][j] = hA;
    hs_lin[w][1][0][j] = hB;
    __syncwarp();

    const float4* xp0 = g_xg0 + b0 * (size_t)(TT * HH);
    const float4* xp1 = g_xg0 + b1 * (size_t)(TT * HH);
    float* op0 = dout + b0 * (size_t)(TT * HH);
    float* op1 = dout + b1 * (size_t)(TT * HH);

    const unsigned int xsbase =
        (unsigned int)__cvta_generic_to_shared(&xstage[0][w][0][j]);

#pragma unroll
    for (int s = 0; s < 3; ++s) {
        if (act) {
            cpasync16(xsbase + (unsigned)s * 4096u,        xp0 + s * HH + j);
            cpasync16(xsbase + (unsigned)s * 4096u + 512u, xp1 + s * HH + j);
        }
        cpcommit();
    }

    int p = 0;
    for (int t = 0; t < TT; ++t) {
        if (t + 3 < TT && act) {
            unsigned int sa = xsbase + (unsigned)((t + 3) & 3) * 4096u;
            cpasync16(sa,        xp0 + (t + 3) * HH + j);
            cpasync16(sa + 512u, xp1 + (t + 3) * HH + j);
        }
        cpcommit();
        cpwait3();
        float4 xvA = xstage[t & 3][w][0][j];
        float4 xvB = xstage[t & 3][w][1][j];

        const ulonglong2* hpA = reinterpret_cast<const ulonglong2*>(&hs2[w][0][p][0]);
        const ulonglong2* hpB = reinterpret_cast<const ulonglong2*>(&hs2[w][1][p][0]);

        unsigned long long aifA = pack2(xvA.x, xvA.y);
        unsigned long long agoA = pack2(xvA.z, xvA.w);
        unsigned long long aifB = pack2(xvB.x, xvB.y);
        unsigned long long agoB = pack2(xvB.z, xvB.w);
#pragma unroll
        for (int q = 0; q < 14; ++q) {
            ulonglong2 h2A = hpA[q];
            ulonglong2 h2B = hpB[q];
            aifA = fma2(h2A.x, wif[2 * q],     aifA);
            agoA = fma2(h2A.x, wgo[2 * q],     agoA);
            aifB = fma2(h2B.x, wif[2 * q],     aifB);
            agoB = fma2(h2B.x, wgo[2 * q],     agoB);
            aifA = fma2(h2A.y, wif[2 * q + 1], aifA);
            agoA = fma2(h2A.y, wgo[2 * q + 1], agoA);
            aifB = fma2(h2B.y, wif[2 * q + 1], aifB);
            agoB = fma2(h2B.y, wgo[2 * q + 1], agoB);
        }

        float ai, af, ag, ao;
        unpack2(aifA, ai, af);
        unpack2(agoA, ag, ao);
        float giA = sigf(ai), gfA = sigf(af), ggA = tanhfast(ag), goA = sigf(ao);
        cA = fmaf(gfA, cA, giA * ggA);
        float hnA = goA * tanhfast(cA);

        unpack2(aifB, ai, af);
        unpack2(agoB, ag, ao);
        float giB = sigf(ai), gfB = sigf(af), ggB = tanhfast(ag), goB = sigf(ao);
        cB = fmaf(gfB, cB, giB * ggB);
        float hnB = goB * tanhfast(cB);

        if (act) {
            hs2[w][0][p ^ 1][j] = pack2(hnA, hnA);
            hs2[w][1][p ^ 1][j] = pack2(hnB, hnB);
            hs_lin[w][0][p ^ 1][j] = hnA;
            hs_lin[w][1][p ^ 1][j] = hnB;
        }
        __syncwarp();

        const float4* hqA = reinterpret_cast<const float4*>(&hs_lin[w][0][p ^ 1][0]);
        const float4* hqB = reinterpret_cast<const float4*>(&hs_lin[w][1][p ^ 1][0]);
        float lA0 = bls[jj], lA1 = 0.f, lB0 = bls[jj], lB1 = 0.f;
#pragma unroll
        for (int q = 0; q < 7; ++q) {
            float4 h4A = hqA[q];
            float4 h4B = hqB[q];
            float4 wl = Wl4[jj][q];
            lA0 = fmaf(wl.x, h4A.x, lA0);
            lA1 = fmaf(wl.y, h4A.y, lA1);
            lA0 = fmaf(wl.z, h4A.z, lA0);
            lA1 = fmaf(wl.w, h4A.w, lA1);
            lB0 = fmaf(wl.x, h4B.x, lB0);
            lB1 = fmaf(wl.y, h4B.y, lB1);
            lB0 = fmaf(wl.z, h4B.z, lB0);
            lB1 = fmaf(wl.w, h4B.w, lB1);
        }
        if (act) {
            op0[t * HH + j] = lA0 + lA1;
            op1[t * HH + j] = lB0 + lB1;
        }

        p ^= 1;
    }
}

// ================= host =================
extern "C" void kernel_launch(void* const* d_in, const int* in_sizes, int n_in,
                              void* d_out, int out_size)
{
    const float* x   = (const float*)d_in[0];
    const float* h0  = (const float*)d_in[1];
    const float* c0  = (const float*)d_in[2];
    const float* Wih = (const float*)d_in[3];
    const float* Whh = (const float*)d_in[4];
    const float* bih = (const float*)d_in[5];
    const float* bhh = (const float*)d_in[6];
    const float* Wl  = (const float*)d_in[7];
    const float* bl  = (const float*)d_in[8];
    float* out = (float*)d_out;

    const size_t st = (size_t)BB * HH;
    const size_t wS = (size_t)GG * HH;
    const size_t bS = (size_t)GG;

    const int gridA = (BB * TT) / AROWS;  // 9984
    const int gridF = BB / 4;             // 8192
    const int gridL = BB / 8;             // 4096

    // Layer 0 feed-forward: x -> xg0
    phaseA_kernel<<<gridA, 128>>>(x, Wih, bih, bhh);
    // Layer 0 recurrence + layer 1 feed-forward: xg0 -> xg1
    fusedB_kernel<<<gridF, 128>>>(h0, c0, Whh,
                                  Wih + wS, bih + bS, bhh + bS, 0);
    // Layer 1 recurrence + layer 2 feed-forward: xg1 -> xg0
    fusedB_kernel<<<gridF, 128>>>(h0 + st, c0 + st, Whh + wS,
                                  Wih + 2 * wS, bih + 2 * bS, bhh + 2 * bS, 1);
    // Layer 2 recurrence + linear head: xg0 -> out
    phaseB_lin_kernel<<<gridL, 128>>>(h0 + 2 * st, c0 + 2 * st, Whh + 2 * wS, Wl, bl, out);
}

// round 9
// speedup vs baseline: 1.7367x; 1.0127x over previous
#include <cuda_runtime.h>

#define BB 32768
#define TT 78
#define HH 27
#define GG 108   // 4*H

// Ping-pong xg buffers (device globals; accessed ONLY from device code)
static __device__ float4 g_xg0[(size_t)BB * TT * HH];
static __device__ float4 g_xg1[(size_t)BB * TT * HH];

__device__ __forceinline__ float sigf(float x) {          // exact (2 MUFU)
    return __fdividef(1.0f, 1.0f + __expf(-x));
}
__device__ __forceinline__ float tapx(float x) {          // 1 MUFU
    float r;
    asm("tanh.approx.f32 %0, %1;" : "=f"(r) : "f"(x));
    return r;
}
__device__ __forceinline__ float sig_apx(float x) {       // 1 MUFU + 2 fma
    return fmaf(0.5f, tapx(0.5f * x), 0.5f);
}

// ---------- packed f32x2 helpers ----------
__device__ __forceinline__ unsigned long long pack2(float lo, float hi) {
    unsigned long long r;
    asm("mov.b64 %0, {%1, %2};" : "=l"(r) : "f"(lo), "f"(hi));
    return r;
}
__device__ __forceinline__ void unpack2(unsigned long long v, float& lo, float& hi) {
    asm("mov.b64 {%0, %1}, %2;" : "=f"(lo), "=f"(hi) : "l"(v));
}
__device__ __forceinline__ unsigned long long fma2(unsigned long long a, unsigned long long b,
                                                   unsigned long long c) {
    unsigned long long d;
    asm("fma.rn.f32x2 %0, %1, %2, %3;" : "=l"(d) : "l"(a), "l"(b), "l"(c));
    return d;
}

// ---------- cp.async helpers ----------
__device__ __forceinline__ void cpasync16(unsigned int saddr, const void* gaddr) {
    asm volatile("cp.async.cg.shared.global [%0], [%1], 16;" :: "r"(saddr), "l"(gaddr));
}
__device__ __forceinline__ void cpcommit() {
    asm volatile("cp.async.commit_group;" ::: "memory");
}
__device__ __forceinline__ void cpwait3() {
    asm volatile("cp.async.wait_group 3;" ::: "memory");
}
__device__ __forceinline__ void barsync(int id, int cnt) {
    asm volatile("bar.sync %0, %1;" :: "r"(id), "r"(cnt) : "memory");
}

// ================= Phase A (layer 0): xg0 = x @ Wih0^T + b =================
// Gate-split warp roles: warp role 0 computes gates (i,f), role 1 gates (g,o),
// each with only 56 weight regs -> 5 blocks/SM (20 warps). x pre-splatted in SMEM
// so the inner loop is pure broadcast LDS.128 + fma2 (no splat MOVs).

#define AROWS 128

__global__ void __launch_bounds__(128, 5)
phaseA_kernel(const float* __restrict__ xin,
              const float* __restrict__ Wih,
              const float* __restrict__ bih,
              const float* __restrict__ bhh)
{
    __shared__ alignas(16) unsigned long long xs2[AROWS * 28];   // 28KB splatted x

    const int tid = threadIdx.x;
    const int w   = tid >> 5;
    const int j   = tid & 31;
    const bool act = (j < HH);
    const int jj = act ? j : 0;
    const int role = w >> 1;      // 0: gates 0,1 (i,f) ; 1: gates 2,3 (g,o)
    const int half = w & 1;       // rowpair group

    const int g0 = role * 2;
    unsigned long long wp[28];
#pragma unroll
    for (int k = 0; k < HH; ++k)
        wp[k] = pack2(Wih[((g0 + 0) * HH + jj) * HH + k],
                      Wih[((g0 + 1) * HH + jj) * HH + k]);
    wp[27] = 0ull;
    const unsigned long long bp = pack2(bih[(g0 + 0) * HH + jj] + bhh[(g0 + 0) * HH + jj],
                                        bih[(g0 + 1) * HH + jj] + bhh[(g0 + 1) * HH + jj]);

    const size_t rowBase = (size_t)blockIdx.x * AROWS;
    const float* gsrc = xin + rowBase * HH;

    // stage pre-splatted (coalesced LDG, conflict-free STS.64)
    for (int i = tid; i < AROWS * HH; i += 128) {
        int r = i / HH, k = i - r * HH;
        float v = gsrc[i];
        xs2[r * 28 + k] = pack2(v, v);
    }
    for (int r = tid; r < AROWS; r += 128) xs2[r * 28 + 27] = 0ull;
    __syncthreads();

#pragma unroll 1
    for (int mi = 0; mi < 32; ++mi) {
        const int rA = (half * 32 + mi) * 2;
        const ulonglong2* pa = reinterpret_cast<const ulonglong2*>(&xs2[rA * 28]);
        const ulonglong2* pb = reinterpret_cast<const ulonglong2*>(&xs2[(rA + 1) * 28]);

        unsigned long long accA = bp, accB = bp;
#pragma unroll
        for (int q = 0; q < 14; ++q) {
            ulonglong2 xa = pa[q];
            ulonglong2 xb = pb[q];
            accA = fma2(xa.x, wp[2 * q],     accA);
            accB = fma2(xb.x, wp[2 * q],     accB);
            accA = fma2(xa.y, wp[2 * q + 1], accA);
            accB = fma2(xb.y, wp[2 * q + 1], accB);
        }

        if (act) {
            float lo, hi;
            unpack2(accA, lo, hi);
            float* d0 = reinterpret_cast<float*>(&g_xg0[(rowBase + rA) * HH + j]);
            *reinterpret_cast<float2*>(d0 + role * 2) = make_float2(lo, hi);
            unpack2(accB, lo, hi);
            float* d1 = reinterpret_cast<float*>(&g_xg0[(rowBase + rA + 1) * HH + j]);
            *reinterpret_cast<float2*>(d1 + role * 2) = make_float2(lo, hi);
        }
    }
}

// ================= Fused: recurrence of layer l (warps 0,1) + feed-forward of
// layer l+1 (warps 2,3), paired by named barrier, pipeline depth 1.

__global__ void __launch_bounds__(128, 3)
fusedB_kernel(const float* __restrict__ h0,
              const float* __restrict__ c0,
              const float* __restrict__ WhhL,
              const float* __restrict__ WihN,
              const float* __restrict__ bihN,
              const float* __restrict__ bhhN,
              int dir)                           // 0: xg0 -> xg1 ; 1: xg1 -> xg0
{
    __shared__ float whh_s[GG * HH];
    __shared__ float wih_s[GG * HH];
    __shared__ alignas(16) unsigned long long hs2[2][2][2][32];
    __shared__ alignas(16) float4 xstage[4][2][2][32];

    const int tid = threadIdx.x;
    const int w   = tid >> 5;
    const int j   = tid & 31;
    const bool act = (j < HH);
    const int jj = act ? j : 0;
    const int pid = w & 1;
    const bool isRec = (w < 2);

    for (int i = tid; i < GG * HH; i += 128) {
        whh_s[i] = WhhL[i];
        wih_s[i] = WihN[i];
    }
    __syncthreads();

    const float* wsrc = isRec ? whh_s : wih_s;
    unsigned long long wif[28], wgo[28];
#pragma unroll
    for (int k = 0; k < HH; ++k) {
        wif[k] = pack2(wsrc[(0 * HH + jj) * HH + k], wsrc[(1 * HH + jj) * HH + k]);
        wgo[k] = pack2(wsrc[(2 * HH + jj) * HH + k], wsrc[(3 * HH + jj) * HH + k]);
    }
    wif[27] = 0ull;
    wgo[27] = 0ull;

    const float4* xsrc = (dir == 0) ? g_xg0 : g_xg1;
    float4*       xdst = (dir == 0) ? g_xg1 : g_xg0;

    const size_t b0 = (size_t)blockIdx.x * 4 + pid * 2;
    const size_t b1 = b0 + 1;

    if (isRec) {
        float cA = act ? c0[b0 * HH + j] : 0.f;
        float cB = act ? c0[b1 * HH + j] : 0.f;
        float hA = act ? h0[b0 * HH + j] : 0.f;
        float hB = act ? h0[b1 * HH + j] : 0.f;
        hs2[pid][0][0][j] = pack2(hA, hA);
        hs2[pid][1][0][j] = pack2(hB, hB);
        __syncwarp();

        const float4* xp0 = xsrc + b0 * (size_t)(TT * HH);
        const float4* xp1 = xsrc + b1 * (size_t)(TT * HH);
        const unsigned int xsbase =
            (unsigned int)__cvta_generic_to_shared(&xstage[0][pid][0][j]);

#pragma unroll
        for (int s = 0; s < 3; ++s) {
            if (act) {
                cpasync16(xsbase + (unsigned)s * 2048u,        xp0 + s * HH + j);
                cpasync16(xsbase + (unsigned)s * 2048u + 512u, xp1 + s * HH + j);
            }
            cpcommit();
        }

        int p = 0;
        for (int t = 0; t < TT; ++t) {
            if (t + 3 < TT && act) {
                unsigned int sa = xsbase + (unsigned)((t + 3) & 3) * 2048u;
                cpasync16(sa,        xp0 + (t + 3) * HH + j);
                cpasync16(sa + 512u, xp1 + (t + 3) * HH + j);
            }
            cpcommit();
            cpwait3();
            float4 xvA = xstage[t & 3][pid][0][j];
            float4 xvB = xstage[t & 3][pid][1][j];

            const ulonglong2* hpA = reinterpret_cast<const ulonglong2*>(&hs2[pid][0][p][0]);
            const ulonglong2* hpB = reinterpret_cast<const ulonglong2*>(&hs2[pid][1][p][0]);

            unsigned long long aifA = pack2(xvA.x, xvA.y);
            unsigned long long agoA = pack2(xvA.z, xvA.w);
            unsigned long long aifB = pack2(xvB.x, xvB.y);
            unsigned long long agoB = pack2(xvB.z, xvB.w);
#pragma unroll
            for (int q = 0; q < 14; ++q) {
                ulonglong2 h2A = hpA[q];
                ulonglong2 h2B = hpB[q];
                aifA = fma2(h2A.x, wif[2 * q],     aifA);
                agoA = fma2(h2A.x, wgo[2 * q],     agoA);
                aifB = fma2(h2B.x, wif[2 * q],     aifB);
                agoB = fma2(h2B.x, wgo[2 * q],     agoB);
                aifA = fma2(h2A.y, wif[2 * q + 1], aifA);
                agoA = fma2(h2A.y, wgo[2 * q + 1], agoA);
                aifB = fma2(h2B.y, wif[2 * q + 1], aifB);
                agoB = fma2(h2B.y, wgo[2 * q + 1], agoB);
            }

            float ai, af, ag, ao;
            unpack2(aifA, ai, af);
            unpack2(agoA, ag, ao);
            float giA = sig_apx(ai), gfA = sigf(af), ggA = tapx(ag), goA = sig_apx(ao);
            cA = fmaf(gfA, cA, giA * ggA);
            float hnA = goA * tapx(cA);

            unpack2(aifB, ai, af);
            unpack2(agoB, ag, ao);
            float giB = sig_apx(ai), gfB = sigf(af), ggB = tapx(ag), goB = sig_apx(ao);
            cB = fmaf(gfB, cB, giB * ggB);
            float hnB = goB * tapx(cB);

            if (act) {
                hs2[pid][0][p ^ 1][j] = pack2(hnA, hnA);
                hs2[pid][1][p ^ 1][j] = pack2(hnB, hnB);
            }
            barsync(2 + pid, 64);
            p ^= 1;
        }
    } else {
        const unsigned long long bif = pack2(bihN[0 * HH + jj] + bhhN[0 * HH + jj],
                                             bihN[1 * HH + jj] + bhhN[1 * HH + jj]);
        const unsigned long long bgo = pack2(bihN[2 * HH + jj] + bhhN[2 * HH + jj],
                                             bihN[3 * HH + jj] + bhhN[3 * HH + jj]);
        float4* op0 = xdst + b0 * (size_t)(TT * HH);
        float4* op1 = xdst + b1 * (size_t)(TT * HH);

        int p = 0;
        for (int t = 0; t < TT; ++t) {
            barsync(2 + pid, 64);

            const ulonglong2* hpA = reinterpret_cast<const ulonglong2*>(&hs2[pid][0][p ^ 1][0]);
            const ulonglong2* hpB = reinterpret_cast<const ulonglong2*>(&hs2[pid][1][p ^ 1][0]);

            unsigned long long aifA = bif, agoA = bgo;
            unsigned long long aifB = bif, agoB = bgo;
#pragma unroll
            for (int q = 0; q < 14; ++q) {
                ulonglong2 h2A = hpA[q];
                ulonglong2 h2B = hpB[q];
                aifA = fma2(h2A.x, wif[2 * q],     aifA);
                agoA = fma2(h2A.x, wgo[2 * q],     agoA);
                aifB = fma2(h2B.x, wif[2 * q],     aifB);
                agoB = fma2(h2B.x, wgo[2 * q],     agoB);
                aifA = fma2(h2A.y, wif[2 * q + 1], aifA);
                agoA = fma2(h2A.y, wgo[2 * q + 1], agoA);
                aifB = fma2(h2B.y, wif[2 * q + 1], aifB);
                agoB = fma2(h2B.y, wgo[2 * q + 1], agoB);
            }

            if (act) {
                float v0, v1, v2, v3;
                unpack2(aifA, v0, v1);
                unpack2(agoA, v2, v3);
                op0[t * HH + j] = make_float4(v0, v1, v2, v3);
                unpack2(aifB, v0, v1);
                unpack2(agoB, v2, v3);
                op1[t * HH + j] = make_float4(v0, v1, v2, v3);
            }
            p ^= 1;
        }
    }
}

// ================= Final layer: recurrence + fused linear head (reads g_xg0) ======

__global__ void __launch_bounds__(128, 3)
phaseB_lin_kernel(const float* __restrict__ h0,
                  const float* __restrict__ c0,
                  const float* __restrict__ Whh,
                  const float* __restrict__ Wl,
                  const float* __restrict__ bl,
                  float* __restrict__ dout)
{
    __shared__ alignas(16) unsigned long long hs2[4][2][2][32];
    __shared__ float whh_s[GG * HH];
    __shared__ alignas(16) float4 xstage[4][4][2][32];
    __shared__ alignas(16) float hs_lin[4][2][2][32];
    __shared__ alignas(16) float4 Wl4[32][8];
    __shared__ float bls[32];

    const int tid = threadIdx.x;
    const int w   = tid >> 5;
    const int j   = tid & 31;
    const bool act = (j < HH);
    const int jj = act ? j : 0;

    for (int i = tid; i < GG * HH; i += 128) whh_s[i] = Whh[i];
    for (int i = tid; i < 32 * 7; i += 128) {
        int r = i / 7, q = i % 7;
        float4 v;
        v.x = (r < HH && 4 * q + 0 < HH) ? Wl[r * HH + 4 * q + 0] : 0.f;
        v.y = (r < HH && 4 * q + 1 < HH) ? Wl[r * HH + 4 * q + 1] : 0.f;
        v.z = (r < HH && 4 * q + 2 < HH) ? Wl[r * HH + 4 * q + 2] : 0.f;
        v.w = (r < HH && 4 * q + 3 < HH) ? Wl[r * HH + 4 * q + 3] : 0.f;
        Wl4[r][q] = v;
    }
    if (tid < 32) bls[tid] = (tid < HH) ? bl[tid] : 0.f;
    __syncthreads();

    unsigned long long wif[28], wgo[28];
#pragma unroll
    for (int k = 0; k < HH; ++k) {
        wif[k] = pack2(whh_s[(0 * HH + jj) * HH + k], whh_s[(1 * HH + jj) * HH + k]);
        wgo[k] = pack2(whh_s[(2 * HH + jj) * HH + k], whh_s[(3 * HH + jj) * HH + k]);
    }
    wif[27] = 0ull;
    wgo[27] = 0ull;

    const size_t b0 = (size_t)blockIdx.x * 8 + w * 2;
    const size_t b1 = b0 + 1;

    float cA = act ? c0[b0 * HH + j] : 0.f;
    float cB = act ? c0[b1 * HH + j] : 0.f;
    float hA = act ? h0[b0 * HH + j] : 0.f;
    float hB = act ? h0[b1 * HH + j] : 0.f;
    hs2[w][0][0][j] = pack2(hA, hA);
    hs2[w][1][0][j] = pack2(hB, hB);
    hs_lin[w][0][0][j] = hA;
    hs_lin[w][1][0][j] = hB;
    __syncwarp();

    const float4* xp0 = g_xg0 + b0 * (size_t)(TT * HH);
    const float4* xp1 = g_xg0 + b1 * (size_t)(TT * HH);
    float* op0 = dout + b0 * (size_t)(TT * HH);
    float* op1 = dout + b1 * (size_t)(TT * HH);

    const unsigned int xsbase =
        (unsigned int)__cvta_generic_to_shared(&xstage[0][w][0][j]);

#pragma unroll
    for (int s = 0; s < 3; ++s) {
        if (act) {
            cpasync16(xsbase + (unsigned)s * 4096u,        xp0 + s * HH + j);
            cpasync16(xsbase + (unsigned)s * 4096u + 512u, xp1 + s * HH + j);
        }
        cpcommit();
    }

    int p = 0;
    for (int t = 0; t < TT; ++t) {
        if (t + 3 < TT && act) {
            unsigned int sa = xsbase + (unsigned)((t + 3) & 3) * 4096u;
            cpasync16(sa,        xp0 + (t + 3) * HH + j);
            cpasync16(sa + 512u, xp1 + (t + 3) * HH + j);
        }
        cpcommit();
        cpwait3();
        float4 xvA = xstage[t & 3][w][0][j];
        float4 xvB = xstage[t & 3][w][1][j];

        const ulonglong2* hpA = reinterpret_cast<const ulonglong2*>(&hs2[w][0][p][0]);
        const ulonglong2* hpB = reinterpret_cast<const ulonglong2*>(&hs2[w][1][p][0]);

        unsigned long long aifA = pack2(xvA.x, xvA.y);
        unsigned long long agoA = pack2(xvA.z, xvA.w);
        unsigned long long aifB = pack2(xvB.x, xvB.y);
        unsigned long long agoB = pack2(xvB.z, xvB.w);
#pragma unroll
        for (int q = 0; q < 14; ++q) {
            ulonglong2 h2A = hpA[q];
            ulonglong2 h2B = hpB[q];
            aifA = fma2(h2A.x, wif[2 * q],     aifA);
            agoA = fma2(h2A.x, wgo[2 * q],     agoA);
            aifB = fma2(h2B.x, wif[2 * q],     aifB);
            agoB = fma2(h2B.x, wgo[2 * q],     agoB);
            aifA = fma2(h2A.y, wif[2 * q + 1], aifA);
            agoA = fma2(h2A.y, wgo[2 * q + 1], agoA);
            aifB = fma2(h2B.y, wif[2 * q + 1], aifB);
            agoB = fma2(h2B.y, wgo[2 * q + 1], agoB);
        }

        float ai, af, ag, ao;
        unpack2(aifA, ai, af);
        unpack2(agoA, ag, ao);
        float giA = sig_apx(ai), gfA = sigf(af), ggA = tapx(ag), goA = sig_apx(ao);
        cA = fmaf(gfA, cA, giA * ggA);
        float hnA = goA * tapx(cA);

        unpack2(aifB, ai, af);
        unpack2(agoB, ag, ao);
        float giB = sig_apx(ai), gfB = sigf(af), ggB = tapx(ag), goB = sig_apx(ao);
        cB = fmaf(gfB, cB, giB * ggB);
        float hnB = goB * tapx(cB);

        if (act) {
            hs2[w][0][p ^ 1][j] = pack2(hnA, hnA);
            hs2[w][1][p ^ 1][j] = pack2(hnB, hnB);
            hs_lin[w][0][p ^ 1][j] = hnA;
            hs_lin[w][1][p ^ 1][j] = hnB;
        }
        __syncwarp();

        const float4* hqA = reinterpret_cast<const float4*>(&hs_lin[w][0][p ^ 1][0]);
        const float4* hqB = reinterpret_cast<const float4*>(&hs_lin[w][1][p ^ 1][0]);
        float lA0 = bls[jj], lA1 = 0.f, lB0 = bls[jj], lB1 = 0.f;
#pragma unroll
        for (int q = 0; q < 7; ++q) {
            float4 h4A = hqA[q];
            float4 h4B = hqB[q];
            float4 wl = Wl4[jj][q];
            lA0 = fmaf(wl.x, h4A.x, lA0);
            lA1 = fmaf(wl.y, h4A.y, lA1);
            lA0 = fmaf(wl.z, h4A.z, lA0);
            lA1 = fmaf(wl.w, h4A.w, lA1);
            lB0 = fmaf(wl.x, h4B.x, lB0);
            lB1 = fmaf(wl.y, h4B.y, lB1);
            lB0 = fmaf(wl.z, h4B.z, lB0);
            lB1 = fmaf(wl.w, h4B.w, lB1);
        }
        if (act) {
            op0[t * HH + j] = lA0 + lA1;
            op1[t * HH + j] = lB0 + lB1;
        }

        p ^= 1;
    }
}

// ================= host =================
extern "C" void kernel_launch(void* const* d_in, const int* in_sizes, int n_in,
                              void* d_out, int out_size)
{
    const float* x   = (const float*)d_in[0];
    const float* h0  = (const float*)d_in[1];
    const float* c0  = (const float*)d_in[2];
    const float* Wih = (const float*)d_in[3];
    const float* Whh = (const float*)d_in[4];
    const float* bih = (const float*)d_in[5];
    const float* bhh = (const float*)d_in[6];
    const float* Wl  = (const float*)d_in[7];
    const float* bl  = (const float*)d_in[8];
    float* out = (float*)d_out;

    const size_t st = (size_t)BB * HH;
    const size_t wS = (size_t)GG * HH;
    const size_t bS = (size_t)GG;

    const int gridA = (BB * TT) / AROWS;  // 19968
    const int gridF = BB / 4;             // 8192
    const int gridL = BB / 8;             // 4096

    phaseA_kernel<<<gridA, 128>>>(x, Wih, bih, bhh);
    fusedB_kernel<<<gridF, 128>>>(h0, c0, Whh,
                                  Wih + wS, bih + bS, bhh + bS, 0);
    fusedB_kernel<<<gridF, 128>>>(h0 + st, c0 + st, Whh + wS,
                                  Wih + 2 * wS, bih + 2 * bS, bhh + 2 * bS, 1);
    phaseB_lin_kernel<<<gridL, 128>>>(h0 + 2 * st, c0 + 2 * st, Whh + 2 * wS, Wl, bl, out);
}

// round 11
// speedup vs baseline: 1.9397x; 1.1169x over previous
#include <cuda_runtime.h>
#include <cuda_bf16.h>
#include <cstdint>

#define BB 32768
#define TT 78
#define HH 27
#define GG 108                 // 4*H
#define NT ((BB * TT) / 128)   // 19968 tiles of 128 rows

// Scratch (device globals; accessed ONLY from device code)
static __device__ float4 g_xg[(size_t)BB * TT * HH];    // gate preactivations (no bias)
static __device__ float  g_hbuf[(size_t)BB * TT * HH];  // inter-layer h

__device__ __forceinline__ float sigf(float x) {          // exact (2 MUFU)
    return __fdividef(1.0f, 1.0f + __expf(-x));
}
__device__ __forceinline__ float tapx(float x) {          // 1 MUFU
    float r;
    asm("tanh.approx.f32 %0, %1;" : "=f"(r) : "f"(x));
    return r;
}
__device__ __forceinline__ float sig_apx(float x) {
    return fmaf(0.5f, tapx(0.5f * x), 0.5f);
}

// ---------- packed f32x2 helpers ----------
__device__ __forceinline__ unsigned long long pack2(float lo, float hi) {
    unsigned long long r;
    asm("mov.b64 %0, {%1, %2};" : "=l"(r) : "f"(lo), "f"(hi));
    return r;
}
__device__ __forceinline__ void unpack2(unsigned long long v, float& lo, float& hi) {
    asm("mov.b64 {%0, %1}, %2;" : "=f"(lo), "=f"(hi) : "l"(v));
}
__device__ __forceinline__ unsigned long long fma2(unsigned long long a, unsigned long long b,
                                                   unsigned long long c) {
    unsigned long long d;
    asm("fma.rn.f32x2 %0, %1, %2, %3;" : "=l"(d) : "l"(a), "l"(b), "l"(c));
    return d;
}
__device__ __forceinline__ unsigned long long add2(unsigned long long a, unsigned long long b) {
    unsigned long long d;
    asm("add.rn.f32x2 %0, %1, %2;" : "=l"(d) : "l"(a), "l"(b));
    return d;
}

// ---------- cp.async helpers ----------
__device__ __forceinline__ void cpasync16(unsigned int saddr, const void* gaddr) {
    asm volatile("cp.async.cg.shared.global [%0], [%1], 16;" :: "r"(saddr), "l"(gaddr));
}
__device__ __forceinline__ void cpcommit() {
    asm volatile("cp.async.commit_group;" ::: "memory");
}
__device__ __forceinline__ void cpwait3() {
    asm volatile("cp.async.wait_group 3;" ::: "memory");
}

__device__ __forceinline__ uint32_t smem_u32(const void* p) {
    uint32_t a;
    asm("{ .reg .u64 t; cvta.to.shared.u64 t, %1; cvt.u32.u64 %0, t; }" : "=r"(a) : "l"(p));
    return a;
}

#define MMA16816(C, A, B)                                                     \
    asm volatile(                                                             \
        "mma.sync.aligned.m16n8k16.row.col.f32.bf16.bf16.f32 "                \
        "{%0,%1,%2,%3},{%4,%5,%6,%7},{%8,%9},{%0,%1,%2,%3};"                  \
        : "+f"((C)[0]), "+f"((C)[1]), "+f"((C)[2]), "+f"((C)[3])              \
        : "r"((A)[0]), "r"((A)[1]), "r"((A)[2]), "r"((A)[3]),                 \
          "r"((B)[0]), "r"((B)[1]))

// ================= MMA feed-forward: xg = in @ Wih^T (bf16 hi/lo split, fp32 acc) ====
// One block per 128-row tile. Warp w owns gate-interleaved cols n in [32w,32w+32),
// n = 4j+g, so the C fragment IS the consumer's gate-packed float4 half.
// K=96 logical: steps (Ahi,Bhi k0/k1), (Ahi,Blo k0/k1), (Alo,Bhi k0/k1).

__global__ void __launch_bounds__(128, 4)
mmaFF_kernel(const float* __restrict__ xin,
             const float* __restrict__ Wih,
             int src)                        // 0: xin, 1: g_hbuf
{
    __shared__ __align__(16) unsigned short As[128 * 64];   // 16KB: cols 0-31 hi, 32-63 lo

    const int tid = threadIdx.x;
    const int w  = tid >> 5;
    const int l  = tid & 31;
    const int lq = l >> 2;    // 0..7
    const int lr = l & 3;     // 0..3

    // ---- B fragments, register-stationary: bf[hi/lo][khalf][ntile][reg] ----
    uint32_t bf[2][2][4][2];
#pragma unroll
    for (int kb = 0; kb < 2; ++kb)
#pragma unroll
    for (int nt = 0; nt < 4; ++nt)
#pragma unroll
    for (int r = 0; r < 2; ++r) {
        const int n = w * 32 + nt * 8 + lq;
        const int j = n >> 2, g = n & 3;
        const int k0 = kb * 16 + r * 8 + 2 * lr;
        float v0 = 0.f, v1 = 0.f;
        if (j < HH) {
            if (k0 < HH)     v0 = Wih[(g * HH + j) * HH + k0];
            if (k0 + 1 < HH) v1 = Wih[(g * HH + j) * HH + k0 + 1];
        }
        __nv_bfloat16 h0 = __float2bfloat16(v0);
        __nv_bfloat16 h1 = __float2bfloat16(v1);
        __nv_bfloat16 e0 = __float2bfloat16(v0 - __bfloat162float(h0));
        __nv_bfloat16 e1 = __float2bfloat16(v1 - __bfloat162float(h1));
        bf[0][kb][nt][r] = ((uint32_t)__bfloat16_as_ushort(h1) << 16) |
                           (uint32_t)__bfloat16_as_ushort(h0);
        bf[1][kb][nt][r] = ((uint32_t)__bfloat16_as_ushort(e1) << 16) |
                           (uint32_t)__bfloat16_as_ushort(e0);
    }

    const float* inb = src ? (const float*)g_hbuf : xin;
    const size_t tile = blockIdx.x;
    const float* rs = inb + tile * (size_t)(128 * HH);

    // ---- A build: zero pads (cols 27-31, 59-63), then hi/lo split, XOR-swizzled ----
    for (int p = tid; p < 128 * 10; p += 128) {
        int r = p / 10, ci = p % 10;
        int col = (ci < 5) ? (27 + ci) : (54 + ci);      // 27..31 and 59..63
        uint32_t byt = (uint32_t)(r * 128 + col * 2) ^ (uint32_t)((r & 7) << 4);
        As[byt >> 1] = 0;
    }
    for (int i = tid; i < 128 * HH; i += 128) {
        int r = i / HH, k = i - r * HH;
        float v = rs[i];
        __nv_bfloat16 h = __float2bfloat16(v);
        __nv_bfloat16 e = __float2bfloat16(v - __bfloat162float(h));
        uint32_t x = (uint32_t)((r & 7) << 4);
        As[((uint32_t)(r * 128 + k * 2) ^ x) >> 1]        = __bfloat16_as_ushort(h);
        As[((uint32_t)(r * 128 + (32 + k) * 2) ^ x) >> 1] = __bfloat16_as_ushort(e);
    }
    __syncthreads();

    const uint32_t smbA = smem_u32(As);
    float4* xg = g_xg + tile * (size_t)(128 * HH);

#pragma unroll 1
    for (int mt = 0; mt < 8; ++mt) {
        const int row0 = mt * 16 + lq;
        const uint32_t xr = (uint32_t)((row0 & 7) << 4);

        // A fragments: {hi k0-15, hi k16-31, lo k0-15, lo k16-31}
        uint32_t A0[4], A1[4], A2[4], A3[4];
        {
            const uint32_t rb0 = (uint32_t)(row0 * 128);
            const uint32_t rb1 = (uint32_t)((row0 + 8) * 128);
#pragma unroll
            for (int s = 0; s < 4; ++s) {
                uint32_t* Af = (s == 0) ? A0 : (s == 1) ? A1 : (s == 2) ? A2 : A3;
                const uint32_t cb = (uint32_t)(s * 32 + 4 * lr);   // byte col base
                uint32_t a0 = smbA + ((rb0 + cb) ^ xr);
                uint32_t a1 = smbA + ((rb1 + cb) ^ xr);
                uint32_t a2 = smbA + ((rb0 + cb + 16) ^ xr);
                uint32_t a3 = smbA + ((rb1 + cb + 16) ^ xr);
                asm("ld.shared.b32 %0,[%1];" : "=r"(Af[0]) : "r"(a0));
                asm("ld.shared.b32 %0,[%1];" : "=r"(Af[1]) : "r"(a1));
                asm("ld.shared.b32 %0,[%1];" : "=r"(Af[2]) : "r"(a2));
                asm("ld.shared.b32 %0,[%1];" : "=r"(Af[3]) : "r"(a3));
            }
        }

        float acc[4][4];
#pragma unroll
        for (int nt = 0; nt < 4; ++nt) {
            acc[nt][0] = acc[nt][1] = acc[nt][2] = acc[nt][3] = 0.f;
            MMA16816(acc[nt], A0, bf[0][0][nt]);   // hi*hi k0-15
            MMA16816(acc[nt], A1, bf[0][1][nt]);   // hi*hi k16-31
            MMA16816(acc[nt], A0, bf[1][0][nt]);   // hi*lo
            MMA16816(acc[nt], A1, bf[1][1][nt]);
            MMA16816(acc[nt], A2, bf[0][0][nt]);   // lo*hi
            MMA16816(acc[nt], A3, bf[0][1][nt]);
        }

        // C -> g_xg: lane fragment (c0,c1)/(c2,c3) is one float2 half of a gate-float4
#pragma unroll
        for (int nt = 0; nt < 4; ++nt) {
            const int jj = 8 * w + 2 * nt + (lr >> 1);
            if (jj < HH) {
                const int gh = lr & 1;   // 0: gates (i,f)=.xy ; 1: gates (g,o)=.zw
                float2* p0 = reinterpret_cast<float2*>(&xg[(size_t)row0 * HH + jj]);
                p0[gh] = make_float2(acc[nt][0], acc[nt][1]);
                float2* p1 = reinterpret_cast<float2*>(&xg[(size_t)(row0 + 8) * HH + jj]);
                p1[gh] = make_float2(acc[nt][2], acc[nt][3]);
            }
        }
    }
}

// ================= Recurrence (2 batch elems/warp; bias folded here) ==================

template<bool DOLIN>
__global__ void __launch_bounds__(128, 3)
phaseB_kernel(const float* __restrict__ h0,
              const float* __restrict__ c0,
              const float* __restrict__ Whh,
              const float* __restrict__ bih,
              const float* __restrict__ bhh,
              const float* __restrict__ Wl,
              const float* __restrict__ bl,
              float* __restrict__ dout)
{
    __shared__ alignas(16) unsigned long long hs2[4][2][2][32];
    __shared__ float whh_s[GG * HH];
    __shared__ alignas(16) float4 xstage[4][4][2][32];
    __shared__ alignas(16) float hs_lin[4][2][2][32];
    __shared__ alignas(16) float4 Wl4[32][8];
    __shared__ float bls[32];

    const int tid = threadIdx.x;
    const int w   = tid >> 5;
    const int j   = tid & 31;
    const bool act = (j < HH);
    const int jj = act ? j : 0;

    for (int i = tid; i < GG * HH; i += 128) whh_s[i] = Whh[i];
    if (DOLIN) {
        for (int i = tid; i < 32 * 7; i += 128) {
            int r = i / 7, q = i % 7;
            float4 v;
            v.x = (r < HH && 4 * q + 0 < HH) ? Wl[r * HH + 4 * q + 0] : 0.f;
            v.y = (r < HH && 4 * q + 1 < HH) ? Wl[r * HH + 4 * q + 1] : 0.f;
            v.z = (r < HH && 4 * q + 2 < HH) ? Wl[r * HH + 4 * q + 2] : 0.f;
            v.w = (r < HH && 4 * q + 3 < HH) ? Wl[r * HH + 4 * q + 3] : 0.f;
            Wl4[r][q] = v;
        }
        if (tid < 32) bls[tid] = (tid < HH) ? bl[tid] : 0.f;
    }
    __syncthreads();

    unsigned long long wif[28], wgo[28];
#pragma unroll
    for (int k = 0; k < HH; ++k) {
        wif[k] = pack2(whh_s[(0 * HH + jj) * HH + k], whh_s[(1 * HH + jj) * HH + k]);
        wgo[k] = pack2(whh_s[(2 * HH + jj) * HH + k], whh_s[(3 * HH + jj) * HH + k]);
    }
    wif[27] = 0ull;
    wgo[27] = 0ull;
    const unsigned long long bif = pack2(bih[0 * HH + jj] + bhh[0 * HH + jj],
                                         bih[1 * HH + jj] + bhh[1 * HH + jj]);
    const unsigned long long bgo = pack2(bih[2 * HH + jj] + bhh[2 * HH + jj],
                                         bih[3 * HH + jj] + bhh[3 * HH + jj]);

    const size_t b0 = (size_t)blockIdx.x * 8 + w * 2;
    const size_t b1 = b0 + 1;

    float cA = act ? c0[b0 * HH + j] : 0.f;
    float cB = act ? c0[b1 * HH + j] : 0.f;
    float hA = act ? h0[b0 * HH + j] : 0.f;
    float hB = act ? h0[b1 * HH + j] : 0.f;
    hs2[w][0][0][j] = pack2(hA, hA);
    hs2[w][1][0][j] = pack2(hB, hB);
    if (DOLIN) { hs_lin[w][0][0][j] = hA; hs_lin[w][1][0][j] = hB; }
    __syncwarp();

    const float4* xp0 = g_xg + b0 * (size_t)(TT * HH);
    const float4* xp1 = g_xg + b1 * (size_t)(TT * HH);
    float* op0 = (DOLIN ? dout : g_hbuf) + b0 * (size_t)(TT * HH);
    float* op1 = (DOLIN ? dout : g_hbuf) + b1 * (size_t)(TT * HH);

    const unsigned int xsbase =
        (unsigned int)__cvta_generic_to_shared(&xstage[0][w][0][j]);

#pragma unroll
    for (int s = 0; s < 3; ++s) {
        if (act) {
            cpasync16(xsbase + (unsigned)s * 4096u,        xp0 + s * HH + j);
            cpasync16(xsbase + (unsigned)s * 4096u + 512u, xp1 + s * HH + j);
        }
        cpcommit();
    }

    int p = 0;
    for (int t = 0; t < TT; ++t) {
        if (t + 3 < TT && act) {
            unsigned int sa = xsbase + (unsigned)((t + 3) & 3) * 4096u;
            cpasync16(sa,        xp0 + (t + 3) * HH + j);
            cpasync16(sa + 512u, xp1 + (t + 3) * HH + j);
        }
        cpcommit();
        cpwait3();
        float4 xvA = xstage[t & 3][w][0][j];
        float4 xvB = xstage[t & 3][w][1][j];

        const ulonglong2* hpA = reinterpret_cast<const ulonglong2*>(&hs2[w][0][p][0]);
        const ulonglong2* hpB = reinterpret_cast<const ulonglong2*>(&hs2[w][1][p][0]);

        unsigned long long aifA = add2(pack2(xvA.x, xvA.y), bif);
        unsigned long long agoA = add2(pack2(xvA.z, xvA.w), bgo);
        unsigned long long aifB = add2(pack2(xvB.x, xvB.y), bif);
        unsigned long long agoB = add2(pack2(xvB.z, xvB.w), bgo);
#pragma unroll
        for (int q = 0; q < 14; ++q) {
            ulonglong2 h2A = hpA[q];
            ulonglong2 h2B = hpB[q];
            aifA = fma2(h2A.x, wif[2 * q],     aifA);
            agoA = fma2(h2A.x, wgo[2 * q],     agoA);
            aifB = fma2(h2B.x, wif[2 * q],     aifB);
            agoB = fma2(h2B.x, wgo[2 * q],     agoB);
            aifA = fma2(h2A.y, wif[2 * q + 1], aifA);
            agoA = fma2(h2A.y, wgo[2 * q + 1], agoA);
            aifB = fma2(h2B.y, wif[2 * q + 1], aifB);
            agoB = fma2(h2B.y, wgo[2 * q + 1], agoB);
        }

        float ai, af, ag, ao;
        unpack2(aifA, ai, af);
        unpack2(agoA, ag, ao);
        float giA = sig_apx(ai), gfA = sigf(af), ggA = tapx(ag), goA = sig_apx(ao);
        cA = fmaf(gfA, cA, giA * ggA);
        float hnA = goA * tapx(cA);

        unpack2(aifB, ai, af);
        unpack2(agoB, ag, ao);
        float giB = sig_apx(ai), gfB = sigf(af), ggB = tapx(ag), goB = sig_apx(ao);
        cB = fmaf(gfB, cB, giB * ggB);
        float hnB = goB * tapx(cB);

        if (act) {
            hs2[w][0][p ^ 1][j] = pack2(hnA, hnA);
            hs2[w][1][p ^ 1][j] = pack2(hnB, hnB);
            if (DOLIN) {
                hs_lin[w][0][p ^ 1][j] = hnA;
                hs_lin[w][1][p ^ 1][j] = hnB;
            }
        }
        __syncwarp();

        if (DOLIN) {
            const float4* hqA = reinterpret_cast<const float4*>(&hs_lin[w][0][p ^ 1][0]);
            const float4* hqB = reinterpret_cast<const float4*>(&hs_lin[w][1][p ^ 1][0]);
            float lA0 = bls[jj], lA1 = 0.f, lB0 = bls[jj], lB1 = 0.f;
#pragma unroll
            for (int q = 0; q < 7; ++q) {
                float4 h4A = hqA[q];
                float4 h4B = hqB[q];
                float4 wl = Wl4[jj][q];
                lA0 = fmaf(wl.x, h4A.x, lA0);
                lA1 = fmaf(wl.y, h4A.y, lA1);
                lA0 = fmaf(wl.z, h4A.z, lA0);
                lA1 = fmaf(wl.w, h4A.w, lA1);
                lB0 = fmaf(wl.x, h4B.x, lB0);
                lB1 = fmaf(wl.y, h4B.y, lB1);
                lB0 = fmaf(wl.z, h4B.z, lB0);
                lB1 = fmaf(wl.w, h4B.w, lB1);
            }
            if (act) {
                op0[t * HH + j] = lA0 + lA1;
                op1[t * HH + j] = lB0 + lB1;
            }
        } else {
            if (act) {
                op0[t * HH + j] = hnA;
                op1[t * HH + j] = hnB;
            }
        }

        p ^= 1;
    }
}

// ================= host =================
extern "C" void kernel_launch(void* const* d_in, const int* in_sizes, int n_in,
                              void* d_out, int out_size)
{
    const float* x   = (const float*)d_in[0];
    const float* h0  = (const float*)d_in[1];
    const float* c0  = (const float*)d_in[2];
    const float* Wih = (const float*)d_in[3];
    const float* Whh = (const float*)d_in[4];
    const float* bih = (const float*)d_in[5];
    const float* bhh = (const float*)d_in[6];
    const float* Wl  = (const float*)d_in[7];
    const float* bl  = (const float*)d_in[8];
    float* out = (float*)d_out;

    const size_t st = (size_t)BB * HH;
    const size_t wS = (size_t)GG * HH;
    const size_t bS = (size_t)GG;

    const int gridB = BB / 8;   // 4096

    // L0: FF (tensor) x -> xg ; rec -> hbuf
    mmaFF_kernel<<<NT, 128>>>(x, Wih, 0);
    phaseB_kernel<false><<<gridB, 128>>>(h0, c0, Whh, bih, bhh, Wl, bl, out);
    // L1: FF hbuf -> xg ; rec -> hbuf
    mmaFF_kernel<<<NT, 128>>>(x, Wih + wS, 1);
    phaseB_kernel<false><<<gridB, 128>>>(h0 + st, c0 + st, Whh + wS,
                                         bih + bS, bhh + bS, Wl, bl, out);
    // L2: FF hbuf -> xg ; rec + linear head -> out
    mmaFF_kernel<<<NT, 128>>>(x, Wih + 2 * wS, 1);
    phaseB_kernel<true><<<gridB, 128>>>(h0 + 2 * st, c0 + 2 * st, Whh + 2 * wS,
                                        bih + 2 * bS, bhh + 2 * bS, Wl, bl, out);
}